// round 2
// baseline (speedup 1.0000x reference)
#include <cuda_runtime.h>
#include <math_constants.h>

#define BB 16
#define TT 2048
#define CC 384
#define DD 64

typedef unsigned long long u64;

// ---- packed f32x2 helpers (FFMA2 path: ptxas never emits these from C++) ----
__device__ __forceinline__ void fma2(u64& d, u64 a, u64 b) {
    asm("fma.rn.f32x2 %0, %1, %2, %0;" : "+l"(d) : "l"(a), "l"(b));
}
__device__ __forceinline__ u64 pack2(float x) {
    u64 r; unsigned int u = __float_as_uint(x);
    asm("mov.b64 %0, {%1, %1};" : "=l"(r) : "r"(u));
    return r;
}
__device__ __forceinline__ void mul2(u64& d, u64 a) {
    asm("mul.rn.f32x2 %0, %0, %1;" : "+l"(d) : "l"(a));
}
__device__ __forceinline__ float2 unpack2(u64 v) {
    unsigned int lo, hi;
    asm("mov.b64 {%0, %1}, %2;" : "=r"(lo), "=r"(hi) : "l"(v));
    float2 f; f.x = __uint_as_float(lo); f.y = __uint_as_float(hi);
    return f;
}

// Scratch for q, k, v projections: [B*T, 64] each
__device__ float g_q[BB * TT * DD];
__device__ float g_k[BB * TT * DD];
__device__ float g_v[BB * TT * DD];

// ---------------------------------------------------------------------------
// Kernel 1: fused QKV projection. 256 blocks, each 128 rows x 192 cols (q|k|v).
// 256 threads, 8x12 micro-tile, f32x2 FMAs. x tile read once per block.
// ---------------------------------------------------------------------------
__global__ __launch_bounds__(256, 1) void proj_kernel(
    const float* __restrict__ x,
    const float* __restrict__ Wq,
    const float* __restrict__ Wk,
    const float* __restrict__ Wv)
{
    __shared__ float xs[128][36];    // 128 rows x 32 k (+4 pad)
    __shared__ float ws[32][196];    // 32 k x 192 cols (+4 pad)

    const int tid = threadIdx.x;
    const int ti = tid >> 4, tj = tid & 15;
    const int r0 = ti * 8;
    const int c0 = tj * 4;
    const int rowBase = blockIdx.x * 128;

    u64 acc[8][6];
#pragma unroll
    for (int i = 0; i < 8; i++)
#pragma unroll
        for (int j = 0; j < 6; j++) acc[i][j] = 0ull;

    const int xr = tid >> 1;
    const int xc = (tid & 1) * 16;
    const int wr = tid >> 3;
    const int wcb = (tid & 7) * 24;

    for (int kk = 0; kk < CC; kk += 32) {
        // load x tile 128x32
#pragma unroll
        for (int u = 0; u < 4; u++)
            *(float4*)&xs[xr][xc + 4 * u] =
                *(const float4*)&x[(rowBase + xr) * CC + kk + xc + 4 * u];
        // load fused W tile 32x192 (cols 0-63: Wq, 64-127: Wk, 128-191: Wv)
#pragma unroll
        for (int u = 0; u < 6; u++) {
            int c = wcb + 4 * u;
            const float* W = (c < 64) ? Wq : (c < 128) ? Wk : Wv;
            *(float4*)&ws[wr][c] = *(const float4*)&W[(kk + wr) * DD + (c & 63)];
        }
        __syncthreads();

#pragma unroll 4
        for (int k = 0; k < 32; k++) {
            u64 ap[8];
#pragma unroll
            for (int i = 0; i < 8; i++) ap[i] = pack2(xs[r0 + i][k]);
            u64 b0 = *(const u64*)&ws[k][c0];
            u64 b1 = *(const u64*)&ws[k][c0 + 2];
            u64 b2 = *(const u64*)&ws[k][64 + c0];
            u64 b3 = *(const u64*)&ws[k][64 + c0 + 2];
            u64 b4 = *(const u64*)&ws[k][128 + c0];
            u64 b5 = *(const u64*)&ws[k][128 + c0 + 2];
#pragma unroll
            for (int i = 0; i < 8; i++) {
                fma2(acc[i][0], ap[i], b0);
                fma2(acc[i][1], ap[i], b1);
                fma2(acc[i][2], ap[i], b2);
                fma2(acc[i][3], ap[i], b3);
                fma2(acc[i][4], ap[i], b4);
                fma2(acc[i][5], ap[i], b5);
            }
        }
        __syncthreads();
    }

#pragma unroll
    for (int i = 0; i < 8; i++) {
        const int row = (rowBase + r0 + i) * DD + c0;
        float2 a0 = unpack2(acc[i][0]), a1 = unpack2(acc[i][1]);
        *(float4*)&g_q[row] = make_float4(a0.x, a0.y, a1.x, a1.y);
        float2 a2 = unpack2(acc[i][2]), a3 = unpack2(acc[i][3]);
        *(float4*)&g_k[row] = make_float4(a2.x, a2.y, a3.x, a3.y);
        float2 a4 = unpack2(acc[i][4]), a5 = unpack2(acc[i][5]);
        *(float4*)&g_v[row] = make_float4(a4.x, a4.y, a5.x, a5.y);
    }
}

// ---------------------------------------------------------------------------
// Kernel 2: flash attention, fp32 with f32x2 FMAs.
// Br=128 q rows per CTA, Bc=128 kv per iter. 256 threads.
// S micro-tile 8x8 (cols 4*tj and 64+4*tj), O micro-tile 8x4.
// Replicates reference quirk: causal-masked OR exactly-zero score -> -inf.
// ---------------------------------------------------------------------------
#define QS 68
#define KS 132
#define VSs 68
#define PSs 132

__global__ __launch_bounds__(256, 1) void attn_kernel(float* __restrict__ out)
{
    extern __shared__ float sm[];
    float* qs  = sm;                      // 128 x 68
    float* kst = qs + 128 * QS;           // 64 x 132 (K transposed [d][s])
    float* vs  = kst + 64 * KS;           // 128 x 68
    float* ps  = vs + 128 * VSs;          // 128 x 132

    const int b   = blockIdx.y;
    const int qt  = 15 - blockIdx.x;      // longest tiles first
    const int tid = threadIdx.x;
    const int ti  = tid >> 4, tj = tid & 15;
    const int r0  = ti * 8;
    const int c0  = tj * 4;
    const int rowg = b * TT + qt * 128;

    const float NEG_INF = -CUDART_INF_F;

    // load q tile (prescaled by 1/8)
    {
        const int r = tid >> 1;
        const int cb = (tid & 1) * 32;
#pragma unroll
        for (int u = 0; u < 8; u++) {
            float4 v = *(const float4*)&g_q[(rowg + r) * DD + cb + 4 * u];
            v.x *= 0.125f; v.y *= 0.125f; v.z *= 0.125f; v.w *= 0.125f;
            *(float4*)&qs[r * QS + cb + 4 * u] = v;
        }
    }

    u64 o2[8][2];
#pragma unroll
    for (int i = 0; i < 8; i++) { o2[i][0] = 0ull; o2[i][1] = 0ull; }
    float m[8], l[8];
#pragma unroll
    for (int i = 0; i < 8; i++) { m[i] = NEG_INF; l[i] = 0.0f; }

    for (int st = 0; st <= qt; st++) {
        __syncthreads();
        // load K (transposed) and V tiles: 128 rows each
        {
            const int s = tid >> 1;
            const int db = (tid & 1) * 32;
            const int srow = (b * TT + st * 128 + s) * DD;
#pragma unroll
            for (int u = 0; u < 8; u++) {
                const int d = db + 4 * u;
                float4 kv = *(const float4*)&g_k[srow + d];
                kst[(d + 0) * KS + s] = kv.x;
                kst[(d + 1) * KS + s] = kv.y;
                kst[(d + 2) * KS + s] = kv.z;
                kst[(d + 3) * KS + s] = kv.w;
                *(float4*)&vs[s * VSs + d] = *(const float4*)&g_v[srow + d];
            }
        }
        __syncthreads();

        // S = q @ K^T : 8 rows x 8 cols per thread (f32x2 pairs)
        u64 s2[8][4];
#pragma unroll
        for (int i = 0; i < 8; i++)
#pragma unroll
            for (int j = 0; j < 4; j++) s2[i][j] = 0ull;

#pragma unroll 4
        for (int d = 0; d < 64; d++) {
            u64 ap[8];
#pragma unroll
            for (int i = 0; i < 8; i++) ap[i] = pack2(qs[(r0 + i) * QS + d]);
            u64 b0 = *(const u64*)&kst[d * KS + c0];
            u64 b1 = *(const u64*)&kst[d * KS + c0 + 2];
            u64 b2 = *(const u64*)&kst[d * KS + 64 + c0];
            u64 b3 = *(const u64*)&kst[d * KS + 64 + c0 + 2];
#pragma unroll
            for (int i = 0; i < 8; i++) {
                fma2(s2[i][0], ap[i], b0);
                fma2(s2[i][1], ap[i], b1);
                fma2(s2[i][2], ap[i], b2);
                fma2(s2[i][3], ap[i], b3);
            }
        }

        // mask + online softmax
        const bool diag = (st == qt);
        const int colA = st * 128 + c0;
        const int colB = colA + 64;
#pragma unroll
        for (int i = 0; i < 8; i++) {
            float sv[8];
            float2 t0 = unpack2(s2[i][0]); sv[0] = t0.x; sv[1] = t0.y;
            float2 t1 = unpack2(s2[i][1]); sv[2] = t1.x; sv[3] = t1.y;
            float2 t2 = unpack2(s2[i][2]); sv[4] = t2.x; sv[5] = t2.y;
            float2 t3 = unpack2(s2[i][3]); sv[6] = t3.x; sv[7] = t3.y;
            const int grow = qt * 128 + r0 + i;
#pragma unroll
            for (int j = 0; j < 4; j++) {
                if ((diag && (colA + j) > grow) || sv[j] == 0.0f) sv[j] = NEG_INF;
                if ((diag && (colB + j) > grow) || sv[4 + j] == 0.0f) sv[4 + j] = NEG_INF;
            }
            float rm = sv[0];
#pragma unroll
            for (int j = 1; j < 8; j++) rm = fmaxf(rm, sv[j]);
#pragma unroll
            for (int msk = 1; msk < 16; msk <<= 1)
                rm = fmaxf(rm, __shfl_xor_sync(0xffffffffu, rm, msk));
            const float mn = fmaxf(m[i], rm);
            const float fac = (m[i] == NEG_INF) ? 0.0f : __expf(m[i] - mn);
            float p[8];
            float psum = 0.0f;
#pragma unroll
            for (int j = 0; j < 8; j++) {
                p[j] = (sv[j] == NEG_INF) ? 0.0f : __expf(sv[j] - mn);
                psum += p[j];
            }
#pragma unroll
            for (int msk = 1; msk < 16; msk <<= 1)
                psum += __shfl_xor_sync(0xffffffffu, psum, msk);
            l[i] = l[i] * fac + psum;
            m[i] = mn;
            u64 fp = pack2(fac);
            mul2(o2[i][0], fp);
            mul2(o2[i][1], fp);
            *(float4*)&ps[(r0 + i) * PSs + c0]      = make_float4(p[0], p[1], p[2], p[3]);
            *(float4*)&ps[(r0 + i) * PSs + 64 + c0] = make_float4(p[4], p[5], p[6], p[7]);
        }
        __syncthreads();

        // O += P @ V : 8 rows x 4 cols per thread
#pragma unroll 4
        for (int s = 0; s < 128; s++) {
            u64 ap[8];
#pragma unroll
            for (int i = 0; i < 8; i++) ap[i] = pack2(ps[(r0 + i) * PSs + s]);
            u64 b0 = *(const u64*)&vs[s * VSs + c0];
            u64 b1 = *(const u64*)&vs[s * VSs + c0 + 2];
#pragma unroll
            for (int i = 0; i < 8; i++) {
                fma2(o2[i][0], ap[i], b0);
                fma2(o2[i][1], ap[i], b1);
            }
        }
    }

    // epilogue: normalize and store
#pragma unroll
    for (int i = 0; i < 8; i++) {
        const float inv = 1.0f / l[i];
        float2 a0 = unpack2(o2[i][0]);
        float2 a1 = unpack2(o2[i][1]);
        *(float4*)&out[(rowg + r0 + i) * DD + c0] =
            make_float4(a0.x * inv, a0.y * inv, a1.x * inv, a1.y * inv);
    }
}

// ---------------------------------------------------------------------------
extern "C" void kernel_launch(void* const* d_in, const int* in_sizes, int n_in,
                              void* d_out, int out_size)
{
    (void)in_sizes; (void)n_in; (void)out_size;
    const float* x  = (const float*)d_in[0];
    const float* Wq = (const float*)d_in[1];
    const float* Wk = (const float*)d_in[2];
    const float* Wv = (const float*)d_in[3];
    float* out = (float*)d_out;

    const int smem_bytes = (128 * QS + 64 * KS + 128 * VSs + 128 * PSs) * (int)sizeof(float);
    cudaFuncSetAttribute(attn_kernel,
                         cudaFuncAttributeMaxDynamicSharedMemorySize, smem_bytes);

    proj_kernel<<<BB * TT / 128, 256>>>(x, Wq, Wk, Wv);
    attn_kernel<<<dim3(TT / 128, BB), 256, smem_bytes>>>(out);
}

// round 3
// speedup vs baseline: 1.3732x; 1.3732x over previous
#include <cuda_runtime.h>
#include <math_constants.h>

#define BB 16
#define TT 2048
#define CC 384
#define DD 64

// Scratch for q, k, v projections: [B*T, 64] each
__device__ float g_q[BB * TT * DD];
__device__ float g_k[BB * TT * DD];
__device__ float g_v[BB * TT * DD];

// ---- tf32 helpers -------------------------------------------------------
__device__ __forceinline__ unsigned tf32r(float f) {
    unsigned h;
    asm("cvt.rna.tf32.f32 %0, %1;" : "=r"(h) : "f"(f));
    return h;
}
__device__ __forceinline__ void split_tf32(float f, unsigned& hi, unsigned& lo) {
    unsigned h;
    asm("cvt.rna.tf32.f32 %0, %1;" : "=r"(h) : "f"(f));
    float r = f - __uint_as_float(h);
    unsigned l;
    asm("cvt.rna.tf32.f32 %0, %1;" : "=r"(l) : "f"(r));
    hi = h; lo = l;
}
__device__ __forceinline__ void mma8(float4& c, const unsigned a[4],
                                     unsigned b0, unsigned b1) {
    asm("mma.sync.aligned.m16n8k8.row.col.f32.tf32.tf32.f32 "
        "{%0,%1,%2,%3},{%4,%5,%6,%7},{%8,%9},{%0,%1,%2,%3};"
        : "+f"(c.x), "+f"(c.y), "+f"(c.z), "+f"(c.w)
        : "r"(a[0]), "r"(a[1]), "r"(a[2]), "r"(a[3]), "r"(b0), "r"(b1));
}

// ---------------------------------------------------------------------------
// Kernel 1: QKV projection (known-good R1 SIMT fp32 version).
// grid = (512 row-tiles, 3 matrices). 64x64 tile, K tiled by 32, 4x4 micro.
// ---------------------------------------------------------------------------
__global__ __launch_bounds__(256) void proj_kernel(
    const float* __restrict__ x,
    const float* __restrict__ Wq,
    const float* __restrict__ Wk,
    const float* __restrict__ Wv)
{
    __shared__ float xs[64][36];
    __shared__ float ws[32][68];

    const float* W;
    float* out;
    if (blockIdx.y == 0)      { W = Wq; out = g_q; }
    else if (blockIdx.y == 1) { W = Wk; out = g_k; }
    else                      { W = Wv; out = g_v; }

    const int tid = threadIdx.x;
    const int ti = tid >> 4, tj = tid & 15;
    const int r0 = ti * 4, c0 = tj * 4;
    const int rowBase = blockIdx.x * 64;

    float acc[4][4];
#pragma unroll
    for (int i = 0; i < 4; i++)
#pragma unroll
        for (int j = 0; j < 4; j++) acc[i][j] = 0.0f;

    const int xr = tid >> 2;
    const int xc = (tid & 3) * 4;
    const int wr = tid >> 3;
    const int wc = (tid & 7) * 4;

    for (int kk = 0; kk < CC; kk += 32) {
        *(float4*)&xs[xr][xc]      = *(const float4*)&x[(rowBase + xr) * CC + kk + xc];
        *(float4*)&xs[xr][xc + 16] = *(const float4*)&x[(rowBase + xr) * CC + kk + xc + 16];
        *(float4*)&ws[wr][wc]      = *(const float4*)&W[(kk + wr) * DD + wc];
        *(float4*)&ws[wr][wc + 32] = *(const float4*)&W[(kk + wr) * DD + wc + 32];
        __syncthreads();

#pragma unroll
        for (int k = 0; k < 32; k++) {
            float a0 = xs[r0 + 0][k];
            float a1 = xs[r0 + 1][k];
            float a2 = xs[r0 + 2][k];
            float a3 = xs[r0 + 3][k];
            float4 bb = *(float4*)&ws[k][c0];
            acc[0][0] += a0 * bb.x; acc[0][1] += a0 * bb.y; acc[0][2] += a0 * bb.z; acc[0][3] += a0 * bb.w;
            acc[1][0] += a1 * bb.x; acc[1][1] += a1 * bb.y; acc[1][2] += a1 * bb.z; acc[1][3] += a1 * bb.w;
            acc[2][0] += a2 * bb.x; acc[2][1] += a2 * bb.y; acc[2][2] += a2 * bb.z; acc[2][3] += a2 * bb.w;
            acc[3][0] += a3 * bb.x; acc[3][1] += a3 * bb.y; acc[3][2] += a3 * bb.z; acc[3][3] += a3 * bb.w;
        }
        __syncthreads();
    }

#pragma unroll
    for (int ii = 0; ii < 4; ii++)
        *(float4*)&out[(rowBase + r0 + ii) * DD + c0] =
            make_float4(acc[ii][0], acc[ii][1], acc[ii][2], acc[ii][3]);
}

// ---------------------------------------------------------------------------
// Kernel 2: flash attention via mma.sync m16n8k8 tf32.
// Br=64 (4 warps x 16 rows), Bc=64, 128 threads.
// QK: 3-term tf32 emulation (fp32-accurate scores). PV: single tf32.
// smem: khi/klo [64][72] (K^T [d][s]), vhi [64][72] ([s][d]), psm [64][68].
// ---------------------------------------------------------------------------
#define KST 72
#define PST 68
#define SMEM_ATTN ((64 * KST * 3 + 64 * PST) * 4)

__global__ __launch_bounds__(128, 3) void attn_kernel(float* __restrict__ out)
{
    extern __shared__ float sm[];
    float* khi = sm;                  // [64][72]  K^T hi
    float* klo = khi + 64 * KST;      // [64][72]  K^T lo
    float* vhi = klo + 64 * KST;      // [64][72]  V  [s][d]
    float* psm = vhi + 64 * KST;      // [64][68]  P (tf32-rounded)

    const int b    = blockIdx.y;
    const int qt   = 31 - blockIdx.x;     // longest first
    const int tid  = threadIdx.x;
    const int lane = tid & 31;
    const int warp = tid >> 5;
    const int lg   = lane >> 2;           // group 0..7
    const int lr   = lane & 3;            // in-group 0..3
    const int rowg = b * TT + qt * 64;
    const int wrow = warp * 16;

    const float NEG_INF = -CUDART_INF_F;

    // ---- Q fragments in registers (hi/lo), scaled by 1/8 ----
    unsigned qh[8][4], ql[8][4];
    {
        const int r1 = (rowg + wrow + lg) * DD;
        const int r2 = r1 + 8 * DD;
#pragma unroll
        for (int t = 0; t < 8; t++) {
            const int c = t * 8 + lr;
            split_tf32(g_q[r1 + c]     * 0.125f, qh[t][0], ql[t][0]);
            split_tf32(g_q[r2 + c]     * 0.125f, qh[t][1], ql[t][1]);
            split_tf32(g_q[r1 + c + 4] * 0.125f, qh[t][2], ql[t][2]);
            split_tf32(g_q[r2 + c + 4] * 0.125f, qh[t][3], ql[t][3]);
        }
    }

    float4 oc[8];
#pragma unroll
    for (int j = 0; j < 8; j++) oc[j] = make_float4(0.f, 0.f, 0.f, 0.f);
    float m1 = NEG_INF, m2 = NEG_INF, l1 = 0.f, l2 = 0.f;

    const int grow1 = qt * 64 + wrow + lg;
    const int grow2 = grow1 + 8;

    for (int st = 0; st <= qt; st++) {
        __syncthreads();
        // ---- stage K (transposed, hi/lo split) and V (tf32) ----
        {
            const int s = tid >> 1;
            const int db = (tid & 1) * 32;
            const int gb = (b * TT + st * 64 + s) * DD + db;
#pragma unroll
            for (int u = 0; u < 8; u++) {
                const int d = db + 4 * u;
                float4 kv = *(const float4*)&g_k[gb + 4 * u];
                unsigned h, lo;
                split_tf32(kv.x, h, lo); khi[(d+0)*KST+s] = __uint_as_float(h); klo[(d+0)*KST+s] = __uint_as_float(lo);
                split_tf32(kv.y, h, lo); khi[(d+1)*KST+s] = __uint_as_float(h); klo[(d+1)*KST+s] = __uint_as_float(lo);
                split_tf32(kv.z, h, lo); khi[(d+2)*KST+s] = __uint_as_float(h); klo[(d+2)*KST+s] = __uint_as_float(lo);
                split_tf32(kv.w, h, lo); khi[(d+3)*KST+s] = __uint_as_float(h); klo[(d+3)*KST+s] = __uint_as_float(lo);
                float4 vv = *(const float4*)&g_v[gb + 4 * u];
                float4 vh = make_float4(__uint_as_float(tf32r(vv.x)), __uint_as_float(tf32r(vv.y)),
                                        __uint_as_float(tf32r(vv.z)), __uint_as_float(tf32r(vv.w)));
                *(float4*)&vhi[s * KST + d] = vh;
            }
        }
        __syncthreads();

        // ---- S = Q K^T (3-term tf32) ----
        float4 sc[8];
#pragma unroll
        for (int j = 0; j < 8; j++) sc[j] = make_float4(0.f, 0.f, 0.f, 0.f);
#pragma unroll
        for (int t = 0; t < 8; t++) {
            const int rb = (t * 8 + lr) * KST + lg;
#pragma unroll
            for (int j = 0; j < 8; j++) {
                const int a0 = rb + j * 8;
                unsigned bh0 = __float_as_uint(khi[a0]);
                unsigned bh1 = __float_as_uint(khi[a0 + 4 * KST]);
                unsigned bl0 = __float_as_uint(klo[a0]);
                unsigned bl1 = __float_as_uint(klo[a0 + 4 * KST]);
                mma8(sc[j], qh[t], bh0, bh1);
                mma8(sc[j], qh[t], bl0, bl1);
                mma8(sc[j], ql[t], bh0, bh1);
            }
        }

        // ---- mask (causal-tile + exact-zero quirk) ----
        const bool diag = (st == qt);
        const int cb = st * 64 + 2 * lr;
#pragma unroll
        for (int j = 0; j < 8; j++) {
            const int c0g = cb + 8 * j;
            if ((diag && c0g     > grow1) || sc[j].x == 0.0f) sc[j].x = NEG_INF;
            if ((diag && c0g + 1 > grow1) || sc[j].y == 0.0f) sc[j].y = NEG_INF;
            if ((diag && c0g     > grow2) || sc[j].z == 0.0f) sc[j].z = NEG_INF;
            if ((diag && c0g + 1 > grow2) || sc[j].w == 0.0f) sc[j].w = NEG_INF;
        }

        // ---- online softmax ----
        float rm1 = NEG_INF, rm2 = NEG_INF;
#pragma unroll
        for (int j = 0; j < 8; j++) {
            rm1 = fmaxf(rm1, fmaxf(sc[j].x, sc[j].y));
            rm2 = fmaxf(rm2, fmaxf(sc[j].z, sc[j].w));
        }
        rm1 = fmaxf(rm1, __shfl_xor_sync(0xffffffffu, rm1, 1));
        rm1 = fmaxf(rm1, __shfl_xor_sync(0xffffffffu, rm1, 2));
        rm2 = fmaxf(rm2, __shfl_xor_sync(0xffffffffu, rm2, 1));
        rm2 = fmaxf(rm2, __shfl_xor_sync(0xffffffffu, rm2, 2));

        const float mn1 = fmaxf(m1, rm1);
        const float mn2 = fmaxf(m2, rm2);
        const float fac1 = (m1 == NEG_INF) ? 0.f : __expf(m1 - mn1);
        const float fac2 = (m2 == NEG_INF) ? 0.f : __expf(m2 - mn2);

        float ps1 = 0.f, ps2 = 0.f;
        const int pb1 = (wrow + lg) * PST + 2 * lr;
        const int pb2 = pb1 + 8 * PST;
#pragma unroll
        for (int j = 0; j < 8; j++) {
            float px = (sc[j].x == NEG_INF) ? 0.f : __expf(sc[j].x - mn1);
            float py = (sc[j].y == NEG_INF) ? 0.f : __expf(sc[j].y - mn1);
            float pz = (sc[j].z == NEG_INF) ? 0.f : __expf(sc[j].z - mn2);
            float pw = (sc[j].w == NEG_INF) ? 0.f : __expf(sc[j].w - mn2);
            ps1 += px + py;
            ps2 += pz + pw;
            float2 h1 = make_float2(__uint_as_float(tf32r(px)), __uint_as_float(tf32r(py)));
            float2 h2 = make_float2(__uint_as_float(tf32r(pz)), __uint_as_float(tf32r(pw)));
            *(float2*)&psm[pb1 + 8 * j] = h1;
            *(float2*)&psm[pb2 + 8 * j] = h2;
        }
        ps1 += __shfl_xor_sync(0xffffffffu, ps1, 1);
        ps1 += __shfl_xor_sync(0xffffffffu, ps1, 2);
        ps2 += __shfl_xor_sync(0xffffffffu, ps2, 1);
        ps2 += __shfl_xor_sync(0xffffffffu, ps2, 2);

        l1 = l1 * fac1 + ps1;  m1 = mn1;
        l2 = l2 * fac2 + ps2;  m2 = mn2;
#pragma unroll
        for (int j = 0; j < 8; j++) {
            oc[j].x *= fac1; oc[j].y *= fac1;
            oc[j].z *= fac2; oc[j].w *= fac2;
        }
        __syncwarp();

        // ---- O += P V (single tf32) ----
#pragma unroll
        for (int t = 0; t < 8; t++) {
            unsigned pa[4];
            const int pb = (wrow + lg) * PST + t * 8 + lr;
            pa[0] = __float_as_uint(psm[pb]);
            pa[1] = __float_as_uint(psm[pb + 8 * PST]);
            pa[2] = __float_as_uint(psm[pb + 4]);
            pa[3] = __float_as_uint(psm[pb + 8 * PST + 4]);
            const int vb = (t * 8 + lr) * KST + lg;
#pragma unroll
            for (int j = 0; j < 8; j++) {
                mma8(oc[j], pa, __float_as_uint(vhi[vb + 8 * j]),
                                __float_as_uint(vhi[vb + 8 * j + 4 * KST]));
            }
        }
    }

    // ---- epilogue ----
    const float inv1 = 1.0f / l1;
    const float inv2 = 1.0f / l2;
    const int ob1 = (rowg + wrow + lg) * DD + 2 * lr;
    const int ob2 = ob1 + 8 * DD;
#pragma unroll
    for (int j = 0; j < 8; j++) {
        *(float2*)&out[ob1 + 8 * j] = make_float2(oc[j].x * inv1, oc[j].y * inv1);
        *(float2*)&out[ob2 + 8 * j] = make_float2(oc[j].z * inv2, oc[j].w * inv2);
    }
}

// ---------------------------------------------------------------------------
extern "C" void kernel_launch(void* const* d_in, const int* in_sizes, int n_in,
                              void* d_out, int out_size)
{
    (void)in_sizes; (void)n_in; (void)out_size;
    const float* x  = (const float*)d_in[0];
    const float* Wq = (const float*)d_in[1];
    const float* Wk = (const float*)d_in[2];
    const float* Wv = (const float*)d_in[3];
    float* out = (float*)d_out;

    cudaFuncSetAttribute(attn_kernel,
                         cudaFuncAttributeMaxDynamicSharedMemorySize, SMEM_ATTN);

    proj_kernel<<<dim3(BB * TT / 64, 3), 256>>>(x, Wq, Wk, Wv);
    attn_kernel<<<dim3(32, BB), 128, SMEM_ATTN>>>(out);
}

// round 4
// speedup vs baseline: 2.0336x; 1.4809x over previous
#include <cuda_runtime.h>
#include <math_constants.h>

#define BB 16
#define TT 2048
#define CC 384
#define DD 64

__device__ float g_q[BB * TT * DD];
__device__ float g_k[BB * TT * DD];
__device__ float g_v[BB * TT * DD];

// ---- bf16 split helpers -------------------------------------------------
// pack(a,b): a -> low half (element 0), b -> high half (element 1)
__device__ __forceinline__ unsigned pack_bf16(float a, float b) {
    unsigned h;
    asm("cvt.rn.bf16x2.f32 %0, %1, %2;" : "=r"(h) : "f"(b), "f"(a));
    return h;
}
// hi = pack(bf16(a), bf16(b)); lo = pack(bf16(a-hi_a), bf16(b-hi_b))
__device__ __forceinline__ void split2(float a, float b, unsigned& hi, unsigned& lo) {
    unsigned h;
    asm("cvt.rn.bf16x2.f32 %0, %1, %2;" : "=r"(h) : "f"(b), "f"(a));
    float ha = __uint_as_float(h << 16);
    float hb = __uint_as_float(h & 0xffff0000u);
    float ra = a - ha;
    float rb = b - hb;
    unsigned l;
    asm("cvt.rn.bf16x2.f32 %0, %1, %2;" : "=r"(l) : "f"(rb), "f"(ra));
    hi = h; lo = l;
}
__device__ __forceinline__ void mma16(float4& c, const unsigned a[4],
                                      unsigned b0, unsigned b1) {
    asm("mma.sync.aligned.m16n8k16.row.col.f32.bf16.bf16.f32 "
        "{%0,%1,%2,%3},{%4,%5,%6,%7},{%8,%9},{%0,%1,%2,%3};"
        : "+f"(c.x), "+f"(c.y), "+f"(c.z), "+f"(c.w)
        : "r"(a[0]), "r"(a[1]), "r"(a[2]), "r"(a[3]), "r"(b0), "r"(b1));
}

// ---------------------------------------------------------------------------
// Kernel 1: fused QKV projection via bf16 3-term mma.
// grid (256 row-blocks of 128, 2 col-blocks of 96). 128 threads, 4 warps.
// Warp tile: 32 rows (2 m16) x 96 cols (12 n8). K stepped by 64 (4 k16 chunks).
// ---------------------------------------------------------------------------
#define XST 132
#define WST 100
#define PROJ_SMEM ((2 * 32 * XST + 2 * 32 * WST) * 4)

__global__ __launch_bounds__(128, 3) void proj_kernel(
    const float* __restrict__ x,
    const float* __restrict__ Wq,
    const float* __restrict__ Wk,
    const float* __restrict__ Wv)
{
    extern __shared__ float psm[];
    float* xph = psm;                 // [32 kp][XST rows]
    float* xpl = xph + 32 * XST;
    float* wph = xpl + 32 * XST;      // [32 kp][WST cols]
    float* wpl = wph + 32 * WST;

    const int tid  = threadIdx.x;
    const int lane = tid & 31, warp = tid >> 5;
    const int lg = lane >> 2, lr = lane & 3;
    const int rowBase = blockIdx.x * 128;
    const int cb = blockIdx.y;        // 96-col block

    float4 acc[2][12];
#pragma unroll
    for (int mt = 0; mt < 2; mt++)
#pragma unroll
        for (int j = 0; j < 12; j++) acc[mt][j] = make_float4(0.f, 0.f, 0.f, 0.f);

    for (int kk = 0; kk < CC; kk += 64) {
        __syncthreads();
        // ---- stage x tile (128 rows x 64 k -> hi/lo bf16x2 pairs, kp-major) ----
        {
            const int r = tid;
            const float* xrow = x + (rowBase + r) * CC + kk;
#pragma unroll
            for (int u = 0; u < 16; u++) {
                float4 v = *(const float4*)(xrow + 4 * u);
                unsigned h0, l0, h1, l1;
                split2(v.x, v.y, h0, l0);
                split2(v.z, v.w, h1, l1);
                xph[(2 * u) * XST + r]     = __uint_as_float(h0);
                xpl[(2 * u) * XST + r]     = __uint_as_float(l0);
                xph[(2 * u + 1) * XST + r] = __uint_as_float(h1);
                xpl[(2 * u + 1) * XST + r] = __uint_as_float(l1);
            }
        }
        // ---- stage W tile (64 k x 96 n -> pairs along k) ----
        {
            const int kp = tid >> 2;
            const int nb = (tid & 3) * 24;
#pragma unroll
            for (int u = 0; u < 6; u++) {
                const int gc = cb * 96 + nb + 4 * u;
                const float* W = (gc < 64) ? Wq : (gc < 128) ? Wk : Wv;
                const int c64 = gc & 63;
                float4 w0 = *(const float4*)&W[(kk + 2 * kp) * DD + c64];
                float4 w1 = *(const float4*)&W[(kk + 2 * kp + 1) * DD + c64];
                float4 hv, lv; unsigned h, l;
                split2(w0.x, w1.x, h, l); hv.x = __uint_as_float(h); lv.x = __uint_as_float(l);
                split2(w0.y, w1.y, h, l); hv.y = __uint_as_float(h); lv.y = __uint_as_float(l);
                split2(w0.z, w1.z, h, l); hv.z = __uint_as_float(h); lv.z = __uint_as_float(l);
                split2(w0.w, w1.w, h, l); hv.w = __uint_as_float(h); lv.w = __uint_as_float(l);
                *(float4*)&wph[kp * WST + nb + 4 * u] = hv;
                *(float4*)&wpl[kp * WST + nb + 4 * u] = lv;
            }
        }
        __syncthreads();

#pragma unroll
        for (int c = 0; c < 4; c++) {
            unsigned ah[2][4], al[2][4];
#pragma unroll
            for (int mt = 0; mt < 2; mt++) {
                const int rb0 = warp * 32 + mt * 16 + lg;
                const int ra = (8 * c + lr) * XST;
                const int rb = (8 * c + lr + 4) * XST;
                ah[mt][0] = __float_as_uint(xph[ra + rb0]);
                ah[mt][1] = __float_as_uint(xph[ra + rb0 + 8]);
                ah[mt][2] = __float_as_uint(xph[rb + rb0]);
                ah[mt][3] = __float_as_uint(xph[rb + rb0 + 8]);
                al[mt][0] = __float_as_uint(xpl[ra + rb0]);
                al[mt][1] = __float_as_uint(xpl[ra + rb0 + 8]);
                al[mt][2] = __float_as_uint(xpl[rb + rb0]);
                al[mt][3] = __float_as_uint(xpl[rb + rb0 + 8]);
            }
#pragma unroll
            for (int j = 0; j < 12; j++) {
                const unsigned bh0 = __float_as_uint(wph[(8 * c + lr) * WST + j * 8 + lg]);
                const unsigned bh1 = __float_as_uint(wph[(8 * c + lr + 4) * WST + j * 8 + lg]);
                const unsigned bl0 = __float_as_uint(wpl[(8 * c + lr) * WST + j * 8 + lg]);
                const unsigned bl1 = __float_as_uint(wpl[(8 * c + lr + 4) * WST + j * 8 + lg]);
#pragma unroll
                for (int mt = 0; mt < 2; mt++) {
                    mma16(acc[mt][j], ah[mt], bh0, bh1);
                    mma16(acc[mt][j], al[mt], bh0, bh1);
                    mma16(acc[mt][j], ah[mt], bl0, bl1);
                }
            }
        }
    }

    // ---- epilogue ----
#pragma unroll
    for (int mt = 0; mt < 2; mt++) {
        const int r0 = rowBase + warp * 32 + mt * 16 + lg;
#pragma unroll
        for (int j = 0; j < 12; j++) {
            const int gc = cb * 96 + j * 8 + 2 * lr;
            float* outp = (gc < 64) ? g_q : (gc < 128) ? g_k : g_v;
            const int c64 = gc & 63;
            *(float2*)&outp[r0 * DD + c64]       = make_float2(acc[mt][j].x, acc[mt][j].y);
            *(float2*)&outp[(r0 + 8) * DD + c64] = make_float2(acc[mt][j].z, acc[mt][j].w);
        }
    }
}

// ---------------------------------------------------------------------------
// Kernel 2: flash attention via bf16 3-term mma (m16n8k16).
// Br=64 (4 warps x 16 rows), Bc=64, 128 threads. P stays in registers.
// K/V staged as hi/lo bf16x2 pairs (packed along the contraction dim).
// ---------------------------------------------------------------------------
#define KVST 72

__global__ __launch_bounds__(128, 3) void attn_kernel(float* __restrict__ out)
{
    __shared__ float khb[32 * KVST];  // K^T hi pairs: [dp][s]
    __shared__ float klb[32 * KVST];  // K^T lo pairs
    __shared__ float vhb[32 * KVST];  // V hi pairs:  [sp][d]
    __shared__ float vlb[32 * KVST];  // V lo pairs

    const int b    = blockIdx.y;
    const int qt   = 31 - blockIdx.x;     // longest first
    const int tid  = threadIdx.x;
    const int lane = tid & 31, warp = tid >> 5;
    const int lg = lane >> 2, lr = lane & 3;
    const int rowg = b * TT + qt * 64;
    const int wrow = warp * 16;

    const float NEG_INF = -CUDART_INF_F;

    // ---- Q fragments (prescaled by 1/8, bf16 hi/lo split) ----
    unsigned qh[4][4], ql[4][4];
    {
        const float* q1 = g_q + (rowg + wrow + lg) * DD;
        const float* q2 = q1 + 8 * DD;
#pragma unroll
        for (int c = 0; c < 4; c++) {
            const int cc = 16 * c + 2 * lr;
            float2 a  = *(const float2*)(q1 + cc);
            float2 bq = *(const float2*)(q2 + cc);
            float2 a8 = *(const float2*)(q1 + cc + 8);
            float2 b8 = *(const float2*)(q2 + cc + 8);
            split2(a.x  * 0.125f, a.y  * 0.125f, qh[c][0], ql[c][0]);
            split2(bq.x * 0.125f, bq.y * 0.125f, qh[c][1], ql[c][1]);
            split2(a8.x * 0.125f, a8.y * 0.125f, qh[c][2], ql[c][2]);
            split2(b8.x * 0.125f, b8.y * 0.125f, qh[c][3], ql[c][3]);
        }
    }

    float4 oc[8];
#pragma unroll
    for (int j = 0; j < 8; j++) oc[j] = make_float4(0.f, 0.f, 0.f, 0.f);
    float m1 = NEG_INF, m2 = NEG_INF, l1 = 0.f, l2 = 0.f;

    const int grow1 = qt * 64 + wrow + lg;
    const int grow2 = grow1 + 8;

    for (int st = 0; st <= qt; st++) {
        __syncthreads();
        // ---- stage K (threads 0-63) and V (threads 64-127) ----
        const int kvbase = (b * TT + st * 64) * DD;
        if (tid < 64) {
            const int s = tid;
            const float* kr = g_k + kvbase + s * DD;
#pragma unroll
            for (int u = 0; u < 16; u++) {
                float4 v = *(const float4*)(kr + 4 * u);
                unsigned h0, l0, h1, l1_;
                split2(v.x, v.y, h0, l0);
                split2(v.z, v.w, h1, l1_);
                khb[(2 * u) * KVST + s]     = __uint_as_float(h0);
                klb[(2 * u) * KVST + s]     = __uint_as_float(l0);
                khb[(2 * u + 1) * KVST + s] = __uint_as_float(h1);
                klb[(2 * u + 1) * KVST + s] = __uint_as_float(l1_);
            }
        } else {
            const int t  = tid - 64;
            const int sp = t >> 1;
            const int dh = (t & 1) * 32;
            const float* v0 = g_v + kvbase + (2 * sp) * DD + dh;
            const float* v1 = v0 + DD;
#pragma unroll
            for (int u = 0; u < 8; u++) {
                float4 a  = *(const float4*)(v0 + 4 * u);
                float4 bv = *(const float4*)(v1 + 4 * u);
                float4 hv, lv; unsigned h, l;
                split2(a.x, bv.x, h, l); hv.x = __uint_as_float(h); lv.x = __uint_as_float(l);
                split2(a.y, bv.y, h, l); hv.y = __uint_as_float(h); lv.y = __uint_as_float(l);
                split2(a.z, bv.z, h, l); hv.z = __uint_as_float(h); lv.z = __uint_as_float(l);
                split2(a.w, bv.w, h, l); hv.w = __uint_as_float(h); lv.w = __uint_as_float(l);
                *(float4*)&vhb[sp * KVST + dh + 4 * u] = hv;
                *(float4*)&vlb[sp * KVST + dh + 4 * u] = lv;
            }
        }
        __syncthreads();

        // ---- S = Q K^T  (3-term bf16) ----
        float4 sc[8];
#pragma unroll
        for (int j = 0; j < 8; j++) sc[j] = make_float4(0.f, 0.f, 0.f, 0.f);
#pragma unroll
        for (int c = 0; c < 4; c++) {
            const int ra = (8 * c + lr) * KVST + lg;
            const int rb = (8 * c + lr + 4) * KVST + lg;
#pragma unroll
            for (int j = 0; j < 8; j++) {
                const unsigned kh0 = __float_as_uint(khb[ra + j * 8]);
                const unsigned kh1 = __float_as_uint(khb[rb + j * 8]);
                const unsigned kl0 = __float_as_uint(klb[ra + j * 8]);
                const unsigned kl1 = __float_as_uint(klb[rb + j * 8]);
                mma16(sc[j], qh[c], kh0, kh1);
                mma16(sc[j], ql[c], kh0, kh1);
                mma16(sc[j], qh[c], kl0, kl1);
            }
        }

        // ---- mask (causal tile + exact-zero quirk) ----
        const bool diag = (st == qt);
        const int cbv = st * 64 + 2 * lr;
#pragma unroll
        for (int j = 0; j < 8; j++) {
            const int c0g = cbv + 8 * j;
            if ((diag && c0g     > grow1) || sc[j].x == 0.0f) sc[j].x = NEG_INF;
            if ((diag && c0g + 1 > grow1) || sc[j].y == 0.0f) sc[j].y = NEG_INF;
            if ((diag && c0g     > grow2) || sc[j].z == 0.0f) sc[j].z = NEG_INF;
            if ((diag && c0g + 1 > grow2) || sc[j].w == 0.0f) sc[j].w = NEG_INF;
        }

        // ---- online softmax ----
        float rm1 = NEG_INF, rm2 = NEG_INF;
#pragma unroll
        for (int j = 0; j < 8; j++) {
            rm1 = fmaxf(rm1, fmaxf(sc[j].x, sc[j].y));
            rm2 = fmaxf(rm2, fmaxf(sc[j].z, sc[j].w));
        }
        rm1 = fmaxf(rm1, __shfl_xor_sync(0xffffffffu, rm1, 1));
        rm1 = fmaxf(rm1, __shfl_xor_sync(0xffffffffu, rm1, 2));
        rm2 = fmaxf(rm2, __shfl_xor_sync(0xffffffffu, rm2, 1));
        rm2 = fmaxf(rm2, __shfl_xor_sync(0xffffffffu, rm2, 2));

        const float mn1 = fmaxf(m1, rm1);
        const float mn2 = fmaxf(m2, rm2);
        const float fac1 = (m1 == NEG_INF) ? 0.f : __expf(m1 - mn1);
        const float fac2 = (m2 == NEG_INF) ? 0.f : __expf(m2 - mn2);

        // exp + P fragments in registers (bf16 hi/lo split)
        unsigned pha[8], phb[8], pla[8], plb[8];
        float ps1 = 0.f, ps2 = 0.f;
#pragma unroll
        for (int j = 0; j < 8; j++) {
            const float px = (sc[j].x == NEG_INF) ? 0.f : __expf(sc[j].x - mn1);
            const float py = (sc[j].y == NEG_INF) ? 0.f : __expf(sc[j].y - mn1);
            const float pz = (sc[j].z == NEG_INF) ? 0.f : __expf(sc[j].z - mn2);
            const float pw = (sc[j].w == NEG_INF) ? 0.f : __expf(sc[j].w - mn2);
            ps1 += px + py;
            ps2 += pz + pw;
            split2(px, py, pha[j], pla[j]);
            split2(pz, pw, phb[j], plb[j]);
        }
        ps1 += __shfl_xor_sync(0xffffffffu, ps1, 1);
        ps1 += __shfl_xor_sync(0xffffffffu, ps1, 2);
        ps2 += __shfl_xor_sync(0xffffffffu, ps2, 1);
        ps2 += __shfl_xor_sync(0xffffffffu, ps2, 2);

        l1 = l1 * fac1 + ps1;  m1 = mn1;
        l2 = l2 * fac2 + ps2;  m2 = mn2;
#pragma unroll
        for (int j = 0; j < 8; j++) {
            oc[j].x *= fac1; oc[j].y *= fac1;
            oc[j].z *= fac2; oc[j].w *= fac2;
        }

        // ---- O += P V  (3-term bf16, A-fragments direct from registers) ----
#pragma unroll
        for (int c = 0; c < 4; c++) {
            const unsigned ah[4] = {pha[2 * c], phb[2 * c], pha[2 * c + 1], phb[2 * c + 1]};
            const unsigned al[4] = {pla[2 * c], plb[2 * c], pla[2 * c + 1], plb[2 * c + 1]};
            const int ra = (8 * c + lr) * KVST + lg;
            const int rb = (8 * c + lr + 4) * KVST + lg;
#pragma unroll
            for (int j = 0; j < 8; j++) {
                const unsigned vh0 = __float_as_uint(vhb[ra + j * 8]);
                const unsigned vh1 = __float_as_uint(vhb[rb + j * 8]);
                const unsigned vl0 = __float_as_uint(vlb[ra + j * 8]);
                const unsigned vl1 = __float_as_uint(vlb[rb + j * 8]);
                mma16(oc[j], ah, vh0, vh1);
                mma16(oc[j], al, vh0, vh1);
                mma16(oc[j], ah, vl0, vl1);
            }
        }
    }

    // ---- epilogue ----
    const float inv1 = 1.0f / l1;
    const float inv2 = 1.0f / l2;
    const int ob1 = (rowg + wrow + lg) * DD + 2 * lr;
    const int ob2 = ob1 + 8 * DD;
#pragma unroll
    for (int j = 0; j < 8; j++) {
        *(float2*)&out[ob1 + 8 * j] = make_float2(oc[j].x * inv1, oc[j].y * inv1);
        *(float2*)&out[ob2 + 8 * j] = make_float2(oc[j].z * inv2, oc[j].w * inv2);
    }
}

// ---------------------------------------------------------------------------
extern "C" void kernel_launch(void* const* d_in, const int* in_sizes, int n_in,
                              void* d_out, int out_size)
{
    (void)in_sizes; (void)n_in; (void)out_size;
    const float* x  = (const float*)d_in[0];
    const float* Wq = (const float*)d_in[1];
    const float* Wk = (const float*)d_in[2];
    const float* Wv = (const float*)d_in[3];
    float* out = (float*)d_out;

    cudaFuncSetAttribute(proj_kernel,
                         cudaFuncAttributeMaxDynamicSharedMemorySize, PROJ_SMEM);

    proj_kernel<<<dim3(BB * TT / 128, 2), 128, PROJ_SMEM>>>(x, Wq, Wk, Wv);
    attn_kernel<<<dim3(32, BB), 128>>>(out);
}

// round 5
// speedup vs baseline: 2.8926x; 1.4224x over previous
#include <cuda_runtime.h>
#include <math_constants.h>

#define BB 16
#define TT 2048
#define CC 384
#define DD 64

// q stays fp32; k/v stored pre-split as packed bf16x2 hi/lo in attn-ready layouts
__device__ float    g_q[BB * TT * DD];
__device__ unsigned g_kh[BB * 32 * TT];        // [b][dp 0..31][t]   pack(k[t][2dp], k[t][2dp+1])
__device__ unsigned g_kl[BB * 32 * TT];
__device__ unsigned g_vh[BB * (TT / 2) * DD];  // [b][tp 0..1023][d] pack(v[2tp][d], v[2tp+1][d])
__device__ unsigned g_vl[BB * (TT / 2) * DD];

// ---- bf16 split helpers -------------------------------------------------
__device__ __forceinline__ void split2(float a, float b, unsigned& hi, unsigned& lo) {
    unsigned h;
    asm("cvt.rn.bf16x2.f32 %0, %1, %2;" : "=r"(h) : "f"(b), "f"(a));
    float ha = __uint_as_float(h << 16);
    float hb = __uint_as_float(h & 0xffff0000u);
    unsigned l;
    asm("cvt.rn.bf16x2.f32 %0, %1, %2;" : "=r"(l) : "f"(b - hb), "f"(a - ha));
    hi = h; lo = l;
}
__device__ __forceinline__ void mma16(float4& c, const unsigned a[4],
                                      unsigned b0, unsigned b1) {
    asm("mma.sync.aligned.m16n8k16.row.col.f32.bf16.bf16.f32 "
        "{%0,%1,%2,%3},{%4,%5,%6,%7},{%8,%9},{%0,%1,%2,%3};"
        : "+f"(c.x), "+f"(c.y), "+f"(c.z), "+f"(c.w)
        : "r"(a[0]), "r"(a[1]), "r"(a[2]), "r"(a[3]), "r"(b0), "r"(b1));
}
__device__ __forceinline__ void cpa16(const float* smem_dst, const void* gsrc) {
    unsigned d = (unsigned)__cvta_generic_to_shared(smem_dst);
    asm volatile("cp.async.cg.shared.global [%0], [%1], 16;" :: "r"(d), "l"(gsrc));
}

// ---------------------------------------------------------------------------
// Kernel 1: fused QKV projection via bf16 3-term mma.
// grid (256 row-blocks of 128, 2 col-blocks of 96). 128 threads, 4 warps.
// Epilogue: q -> fp32; k -> packed [dp][t]; v -> packed [tp][d] (shfl pairing).
// ---------------------------------------------------------------------------
#define XST 132
#define WST 100
#define PROJ_SMEM ((2 * 32 * XST + 2 * 32 * WST) * 4)

__global__ __launch_bounds__(128, 3) void proj_kernel(
    const float* __restrict__ x,
    const float* __restrict__ Wq,
    const float* __restrict__ Wk,
    const float* __restrict__ Wv)
{
    extern __shared__ float psm[];
    float* xph = psm;
    float* xpl = xph + 32 * XST;
    float* wph = xpl + 32 * XST;
    float* wpl = wph + 32 * WST;

    const int tid  = threadIdx.x;
    const int lane = tid & 31, warp = tid >> 5;
    const int lg = lane >> 2, lr = lane & 3;
    const int rowBase = blockIdx.x * 128;
    const int cb = blockIdx.y;

    float4 acc[2][12];
#pragma unroll
    for (int mt = 0; mt < 2; mt++)
#pragma unroll
        for (int j = 0; j < 12; j++) acc[mt][j] = make_float4(0.f, 0.f, 0.f, 0.f);

    for (int kk = 0; kk < CC; kk += 64) {
        __syncthreads();
        {
            const int r = tid;
            const float* xrow = x + (rowBase + r) * CC + kk;
#pragma unroll
            for (int u = 0; u < 16; u++) {
                float4 v = *(const float4*)(xrow + 4 * u);
                unsigned h0, l0, h1, l1;
                split2(v.x, v.y, h0, l0);
                split2(v.z, v.w, h1, l1);
                xph[(2 * u) * XST + r]     = __uint_as_float(h0);
                xpl[(2 * u) * XST + r]     = __uint_as_float(l0);
                xph[(2 * u + 1) * XST + r] = __uint_as_float(h1);
                xpl[(2 * u + 1) * XST + r] = __uint_as_float(l1);
            }
        }
        {
            const int kp = tid >> 2;
            const int nb = (tid & 3) * 24;
#pragma unroll
            for (int u = 0; u < 6; u++) {
                const int gc = cb * 96 + nb + 4 * u;
                const float* W = (gc < 64) ? Wq : (gc < 128) ? Wk : Wv;
                const int c64 = gc & 63;
                float4 w0 = *(const float4*)&W[(kk + 2 * kp) * DD + c64];
                float4 w1 = *(const float4*)&W[(kk + 2 * kp + 1) * DD + c64];
                float4 hv, lv; unsigned h, l;
                split2(w0.x, w1.x, h, l); hv.x = __uint_as_float(h); lv.x = __uint_as_float(l);
                split2(w0.y, w1.y, h, l); hv.y = __uint_as_float(h); lv.y = __uint_as_float(l);
                split2(w0.z, w1.z, h, l); hv.z = __uint_as_float(h); lv.z = __uint_as_float(l);
                split2(w0.w, w1.w, h, l); hv.w = __uint_as_float(h); lv.w = __uint_as_float(l);
                *(float4*)&wph[kp * WST + nb + 4 * u] = hv;
                *(float4*)&wpl[kp * WST + nb + 4 * u] = lv;
            }
        }
        __syncthreads();

#pragma unroll
        for (int c = 0; c < 4; c++) {
            unsigned ah[2][4], al[2][4];
#pragma unroll
            for (int mt = 0; mt < 2; mt++) {
                const int rb0 = warp * 32 + mt * 16 + lg;
                const int ra = (8 * c + lr) * XST;
                const int rb = (8 * c + lr + 4) * XST;
                ah[mt][0] = __float_as_uint(xph[ra + rb0]);
                ah[mt][1] = __float_as_uint(xph[ra + rb0 + 8]);
                ah[mt][2] = __float_as_uint(xph[rb + rb0]);
                ah[mt][3] = __float_as_uint(xph[rb + rb0 + 8]);
                al[mt][0] = __float_as_uint(xpl[ra + rb0]);
                al[mt][1] = __float_as_uint(xpl[ra + rb0 + 8]);
                al[mt][2] = __float_as_uint(xpl[rb + rb0]);
                al[mt][3] = __float_as_uint(xpl[rb + rb0 + 8]);
            }
#pragma unroll
            for (int j = 0; j < 12; j++) {
                const unsigned bh0 = __float_as_uint(wph[(8 * c + lr) * WST + j * 8 + lg]);
                const unsigned bh1 = __float_as_uint(wph[(8 * c + lr + 4) * WST + j * 8 + lg]);
                const unsigned bl0 = __float_as_uint(wpl[(8 * c + lr) * WST + j * 8 + lg]);
                const unsigned bl1 = __float_as_uint(wpl[(8 * c + lr + 4) * WST + j * 8 + lg]);
#pragma unroll
                for (int mt = 0; mt < 2; mt++) {
                    mma16(acc[mt][j], ah[mt], bh0, bh1);
                    mma16(acc[mt][j], al[mt], bh0, bh1);
                    mma16(acc[mt][j], ah[mt], bl0, bl1);
                }
            }
        }
    }

    // ---- epilogue: route to q(fp32) / k(packed [dp][t]) / v(packed [tp][d]) ----
#pragma unroll
    for (int mt = 0; mt < 2; mt++) {
        const int r0 = rowBase + warp * 32 + mt * 16 + lg;   // global row (lg parity = row parity)
        const int b  = r0 >> 11;
        const int t  = r0 & 2047;
#pragma unroll
        for (int j = 0; j < 12; j++) {
            const int gc = cb * 96 + j * 8 + 2 * lr;
            float4 a = acc[mt][j];
            if (gc < 64) {
                *(float2*)&g_q[r0 * DD + gc]       = make_float2(a.x, a.y);
                *(float2*)&g_q[(r0 + 8) * DD + gc] = make_float2(a.z, a.w);
            } else if (gc < 128) {
                const int dp = (gc - 64) >> 1;
                unsigned h, l;
                split2(a.x, a.y, h, l);
                g_kh[((size_t)b * 32 + dp) * 2048 + t] = h;
                g_kl[((size_t)b * 32 + dp) * 2048 + t] = l;
                split2(a.z, a.w, h, l);
                g_kh[((size_t)b * 32 + dp) * 2048 + t + 8] = h;
                g_kl[((size_t)b * 32 + dp) * 2048 + t + 8] = l;
            } else {
                const int d = gc - 128;
                // pair rows (2i, 2i+1): partner lane = lane ^ 4
                float ox = __shfl_xor_sync(0xffffffffu, a.x, 4);
                float oy = __shfl_xor_sync(0xffffffffu, a.y, 4);
                float oz = __shfl_xor_sync(0xffffffffu, a.z, 4);
                float ow = __shfl_xor_sync(0xffffffffu, a.w, 4);
                if ((lg & 1) == 0) {
                    unsigned h0, l0, h1, l1;
                    const int sp0 = r0 >> 1;         // rows (r0, r0+1)
                    split2(a.x, ox, h0, l0);
                    split2(a.y, oy, h1, l1);
                    *(uint2*)&g_vh[(size_t)sp0 * DD + d] = make_uint2(h0, h1);
                    *(uint2*)&g_vl[(size_t)sp0 * DD + d] = make_uint2(l0, l1);
                    const int sp1 = (r0 + 8) >> 1;   // rows (r0+8, r0+9)
                    split2(a.z, oz, h0, l0);
                    split2(a.w, ow, h1, l1);
                    *(uint2*)&g_vh[(size_t)sp1 * DD + d] = make_uint2(h0, h1);
                    *(uint2*)&g_vl[(size_t)sp1 * DD + d] = make_uint2(l0, l1);
                }
            }
        }
    }
}

// ---------------------------------------------------------------------------
// Kernel 2: flash attention, bf16 3-term mma (m16n8k16), pre-split K/V,
// cp.async double-buffered staging. Br=64 (4 warps), Bc=64, 128 threads.
// smem per buffer: 4 arrays x [32][72] floats = 36 KB; x2 buffers = 72 KB.
// ---------------------------------------------------------------------------
#define KVS 72
#define ARR (32 * KVS)
#define ATTN_SMEM (2 * 4 * ARR * 4)

__global__ __launch_bounds__(128, 3) void attn_kernel(float* __restrict__ out)
{
    extern __shared__ float sm[];

    const int b    = blockIdx.y;
    const int qt   = 31 - blockIdx.x;
    const int tid  = threadIdx.x;
    const int lane = tid & 31, warp = tid >> 5;
    const int lg = lane >> 2, lr = lane & 3;
    const int rowg = b * TT + qt * 64;
    const int wrow = warp * 16;

    const unsigned* gkh = g_kh + (size_t)b * 32 * 2048;
    const unsigned* gkl = g_kl + (size_t)b * 32 * 2048;
    const unsigned* gvh = g_vh + (size_t)b * 1024 * DD;
    const unsigned* gvl = g_vl + (size_t)b * 1024 * DD;

    const float NEG_INF = -CUDART_INF_F;

    // ---- stage helper: copy tile st into buffer buf (16 cp.async / thread) ----
    auto stage = [&](int buf, int st) {
        float* kh = sm + (buf * 4 + 0) * ARR;
        float* kl = sm + (buf * 4 + 1) * ARR;
        float* vh = sm + (buf * 4 + 2) * ARR;
        float* vl = sm + (buf * 4 + 3) * ARR;
#pragma unroll
        for (int u = 0; u < 4; u++) {
            const int cid = tid + 128 * u;       // 0..511 16B chunks
            const int row = cid >> 4;            // 0..31
            const int off = (cid & 15) * 4;      // float offset 0..60
            cpa16(kh + row * KVS + off, gkh + row * 2048 + st * 64 + off);
            cpa16(kl + row * KVS + off, gkl + row * 2048 + st * 64 + off);
            cpa16(vh + row * KVS + off, gvh + (st * 32 + row) * DD + off);
            cpa16(vl + row * KVS + off, gvl + (st * 32 + row) * DD + off);
        }
        asm volatile("cp.async.commit_group;" ::: "memory");
    };

    // ---- Q fragments (prescaled by 1/8, bf16 hi/lo split) ----
    unsigned qh[4][4], ql[4][4];
    {
        const float* q1 = g_q + (rowg + wrow + lg) * DD;
        const float* q2 = q1 + 8 * DD;
#pragma unroll
        for (int c = 0; c < 4; c++) {
            const int cc = 16 * c + 2 * lr;
            float2 a  = *(const float2*)(q1 + cc);
            float2 bq = *(const float2*)(q2 + cc);
            float2 a8 = *(const float2*)(q1 + cc + 8);
            float2 b8 = *(const float2*)(q2 + cc + 8);
            split2(a.x  * 0.125f, a.y  * 0.125f, qh[c][0], ql[c][0]);
            split2(bq.x * 0.125f, bq.y * 0.125f, qh[c][1], ql[c][1]);
            split2(a8.x * 0.125f, a8.y * 0.125f, qh[c][2], ql[c][2]);
            split2(b8.x * 0.125f, b8.y * 0.125f, qh[c][3], ql[c][3]);
        }
    }

    float4 oc[8];
#pragma unroll
    for (int j = 0; j < 8; j++) oc[j] = make_float4(0.f, 0.f, 0.f, 0.f);
    float m1 = NEG_INF, m2 = NEG_INF, l1 = 0.f, l2 = 0.f;

    const int grow1 = qt * 64 + wrow + lg;
    const int grow2 = grow1 + 8;

    stage(0, 0);
    int buf = 0;

    for (int st = 0; st <= qt; st++) {
        asm volatile("cp.async.wait_group 0;" ::: "memory");
        __syncthreads();
        if (st < qt) stage(buf ^ 1, st + 1);

        const float* khb = sm + (buf * 4 + 0) * ARR;
        const float* klb = sm + (buf * 4 + 1) * ARR;
        const float* vhb = sm + (buf * 4 + 2) * ARR;
        const float* vlb = sm + (buf * 4 + 3) * ARR;

        // ---- S = Q K^T (3-term bf16) ----
        float4 sc[8];
#pragma unroll
        for (int j = 0; j < 8; j++) sc[j] = make_float4(0.f, 0.f, 0.f, 0.f);
#pragma unroll
        for (int c = 0; c < 4; c++) {
            const int ra = (8 * c + lr) * KVS + lg;
            const int rb = (8 * c + lr + 4) * KVS + lg;
#pragma unroll
            for (int j = 0; j < 8; j++) {
                const unsigned kh0 = __float_as_uint(khb[ra + j * 8]);
                const unsigned kh1 = __float_as_uint(khb[rb + j * 8]);
                const unsigned kl0 = __float_as_uint(klb[ra + j * 8]);
                const unsigned kl1 = __float_as_uint(klb[rb + j * 8]);
                mma16(sc[j], qh[c], kh0, kh1);
                mma16(sc[j], ql[c], kh0, kh1);
                mma16(sc[j], qh[c], kl0, kl1);
            }
        }

        // ---- mask (causal tile + exact-zero quirk) ----
        const bool diag = (st == qt);
        const int cbv = st * 64 + 2 * lr;
#pragma unroll
        for (int j = 0; j < 8; j++) {
            const int c0g = cbv + 8 * j;
            if ((diag && c0g     > grow1) || sc[j].x == 0.0f) sc[j].x = NEG_INF;
            if ((diag && c0g + 1 > grow1) || sc[j].y == 0.0f) sc[j].y = NEG_INF;
            if ((diag && c0g     > grow2) || sc[j].z == 0.0f) sc[j].z = NEG_INF;
            if ((diag && c0g + 1 > grow2) || sc[j].w == 0.0f) sc[j].w = NEG_INF;
        }

        // ---- online softmax ----
        float rm1 = NEG_INF, rm2 = NEG_INF;
#pragma unroll
        for (int j = 0; j < 8; j++) {
            rm1 = fmaxf(rm1, fmaxf(sc[j].x, sc[j].y));
            rm2 = fmaxf(rm2, fmaxf(sc[j].z, sc[j].w));
        }
        rm1 = fmaxf(rm1, __shfl_xor_sync(0xffffffffu, rm1, 1));
        rm1 = fmaxf(rm1, __shfl_xor_sync(0xffffffffu, rm1, 2));
        rm2 = fmaxf(rm2, __shfl_xor_sync(0xffffffffu, rm2, 1));
        rm2 = fmaxf(rm2, __shfl_xor_sync(0xffffffffu, rm2, 2));

        const float mn1 = fmaxf(m1, rm1);
        const float mn2 = fmaxf(m2, rm2);
        const float fac1 = (m1 == NEG_INF) ? 0.f : __expf(m1 - mn1);
        const float fac2 = (m2 == NEG_INF) ? 0.f : __expf(m2 - mn2);

        unsigned pha[8], phb[8], pla[8], plb[8];
        float ps1 = 0.f, ps2 = 0.f;
#pragma unroll
        for (int j = 0; j < 8; j++) {
            const float px = (sc[j].x == NEG_INF) ? 0.f : __expf(sc[j].x - mn1);
            const float py = (sc[j].y == NEG_INF) ? 0.f : __expf(sc[j].y - mn1);
            const float pz = (sc[j].z == NEG_INF) ? 0.f : __expf(sc[j].z - mn2);
            const float pw = (sc[j].w == NEG_INF) ? 0.f : __expf(sc[j].w - mn2);
            ps1 += px + py;
            ps2 += pz + pw;
            split2(px, py, pha[j], pla[j]);
            split2(pz, pw, phb[j], plb[j]);
        }
        ps1 += __shfl_xor_sync(0xffffffffu, ps1, 1);
        ps1 += __shfl_xor_sync(0xffffffffu, ps1, 2);
        ps2 += __shfl_xor_sync(0xffffffffu, ps2, 1);
        ps2 += __shfl_xor_sync(0xffffffffu, ps2, 2);

        l1 = l1 * fac1 + ps1;  m1 = mn1;
        l2 = l2 * fac2 + ps2;  m2 = mn2;
#pragma unroll
        for (int j = 0; j < 8; j++) {
            oc[j].x *= fac1; oc[j].y *= fac1;
            oc[j].z *= fac2; oc[j].w *= fac2;
        }

        // ---- O += P V (3-term bf16, A-fragments from registers) ----
#pragma unroll
        for (int c = 0; c < 4; c++) {
            const unsigned ah[4] = {pha[2 * c], phb[2 * c], pha[2 * c + 1], phb[2 * c + 1]};
            const unsigned al[4] = {pla[2 * c], plb[2 * c], pla[2 * c + 1], plb[2 * c + 1]};
            const int ra = (8 * c + lr) * KVS + lg;
            const int rb = (8 * c + lr + 4) * KVS + lg;
#pragma unroll
            for (int j = 0; j < 8; j++) {
                const unsigned vh0 = __float_as_uint(vhb[ra + j * 8]);
                const unsigned vh1 = __float_as_uint(vhb[rb + j * 8]);
                const unsigned vl0 = __float_as_uint(vlb[ra + j * 8]);
                const unsigned vl1 = __float_as_uint(vlb[rb + j * 8]);
                mma16(oc[j], ah, vh0, vh1);
                mma16(oc[j], al, vh0, vh1);
                mma16(oc[j], ah, vl0, vl1);
            }
        }
        buf ^= 1;
    }

    // ---- epilogue ----
    const float inv1 = 1.0f / l1;
    const float inv2 = 1.0f / l2;
    const int ob1 = (rowg + wrow + lg) * DD + 2 * lr;
    const int ob2 = ob1 + 8 * DD;
#pragma unroll
    for (int j = 0; j < 8; j++) {
        *(float2*)&out[ob1 + 8 * j] = make_float2(oc[j].x * inv1, oc[j].y * inv1);
        *(float2*)&out[ob2 + 8 * j] = make_float2(oc[j].z * inv2, oc[j].w * inv2);
    }
}

// ---------------------------------------------------------------------------
extern "C" void kernel_launch(void* const* d_in, const int* in_sizes, int n_in,
                              void* d_out, int out_size)
{
    (void)in_sizes; (void)n_in; (void)out_size;
    const float* x  = (const float*)d_in[0];
    const float* Wq = (const float*)d_in[1];
    const float* Wk = (const float*)d_in[2];
    const float* Wv = (const float*)d_in[3];
    float* out = (float*)d_out;

    cudaFuncSetAttribute(proj_kernel,
                         cudaFuncAttributeMaxDynamicSharedMemorySize, PROJ_SMEM);
    cudaFuncSetAttribute(attn_kernel,
                         cudaFuncAttributeMaxDynamicSharedMemorySize, ATTN_SMEM);

    proj_kernel<<<dim3(BB * TT / 128, 2), 128, PROJ_SMEM>>>(x, Wq, Wk, Wv);
    attn_kernel<<<dim3(32, BB), 128, ATTN_SMEM>>>(out);
}

// round 6
// speedup vs baseline: 3.5273x; 1.2194x over previous
#include <cuda_runtime.h>
#include <math_constants.h>

#define BB 16
#define TT 2048
#define CC 384
#define DD 64

// q fp32; k/v pre-split packed bf16x2 hi/lo in attn-ready layouts
__device__ float    g_q[BB * TT * DD];
__device__ unsigned g_kh[BB * 32 * TT];        // [b][dp][t]
__device__ unsigned g_kl[BB * 32 * TT];
__device__ unsigned g_vh[BB * (TT / 2) * DD];  // [b][tp][d]
__device__ unsigned g_vl[BB * (TT / 2) * DD];
// fused W pre-split: [kp 0..191][n 0..191] (n: 0-63 Wq, 64-127 Wk, 128-191 Wv)
__device__ unsigned g_wh[192 * 192];
__device__ unsigned g_wl[192 * 192];

// ---- bf16 split helpers -------------------------------------------------
__device__ __forceinline__ void split2(float a, float b, unsigned& hi, unsigned& lo) {
    unsigned h;
    asm("cvt.rn.bf16x2.f32 %0, %1, %2;" : "=r"(h) : "f"(b), "f"(a));
    float ha = __uint_as_float(h << 16);
    float hb = __uint_as_float(h & 0xffff0000u);
    unsigned l;
    asm("cvt.rn.bf16x2.f32 %0, %1, %2;" : "=r"(l) : "f"(b - hb), "f"(a - ha));
    hi = h; lo = l;
}
__device__ __forceinline__ void mma16(float4& c, const unsigned a[4],
                                      unsigned b0, unsigned b1) {
    asm("mma.sync.aligned.m16n8k16.row.col.f32.bf16.bf16.f32 "
        "{%0,%1,%2,%3},{%4,%5,%6,%7},{%8,%9},{%0,%1,%2,%3};"
        : "+f"(c.x), "+f"(c.y), "+f"(c.z), "+f"(c.w)
        : "r"(a[0]), "r"(a[1]), "r"(a[2]), "r"(a[3]), "r"(b0), "r"(b1));
}
__device__ __forceinline__ void cpa16(const void* smem_dst, const void* gsrc) {
    unsigned d = (unsigned)__cvta_generic_to_shared(smem_dst);
    asm volatile("cp.async.cg.shared.global [%0], [%1], 16;" :: "r"(d), "l"(gsrc));
}

// ---------------------------------------------------------------------------
// Kernel 0: one-shot W split. 192 blocks x 192 threads.
// ---------------------------------------------------------------------------
__global__ void wsplit_kernel(const float* __restrict__ Wq,
                              const float* __restrict__ Wk,
                              const float* __restrict__ Wv)
{
    const int kp = blockIdx.x;
    const int n  = threadIdx.x;
    const float* W = (n < 64) ? Wq : (n < 128) ? Wk : Wv;
    const int c = n & 63;
    unsigned h, l;
    split2(W[(2 * kp) * DD + c], W[(2 * kp + 1) * DD + c], h, l);
    g_wh[kp * 192 + n] = h;
    g_wl[kp * 192 + n] = l;
}

// ---------------------------------------------------------------------------
// Kernel 1: fused QKV projection, bf16 3-term mma.
// grid (256 row-blocks of 128, 2 col-blocks of 96). 128 threads, 4 warps.
// x staged RAW via cp.async (split inline at fragment build); W staged
// pre-split via cp.async. Epilogue routes q->fp32, k/v->packed layouts.
// ---------------------------------------------------------------------------
#define XSR 68
#define WST 100
#define PROJ_SMEM ((128 * XSR + 2 * 32 * WST) * 4)

__global__ __launch_bounds__(128, 3) void proj_kernel(const float* __restrict__ x)
{
    extern __shared__ float psm[];
    float* xs  = psm;                 // [128 rows][XSR] raw fp32 x
    float* wph = xs + 128 * XSR;      // [32 kp][WST] packed hi
    float* wpl = wph + 32 * WST;      // [32 kp][WST] packed lo

    const int tid  = threadIdx.x;
    const int lane = tid & 31, warp = tid >> 5;
    const int lg = lane >> 2, lr = lane & 3;
    const int rowBase = blockIdx.x * 128;
    const int cb = blockIdx.y;

    float4 acc[2][12];
#pragma unroll
    for (int mt = 0; mt < 2; mt++)
#pragma unroll
        for (int j = 0; j < 12; j++) acc[mt][j] = make_float4(0.f, 0.f, 0.f, 0.f);

    for (int kk = 0; kk < CC; kk += 64) {
        // ---- stage: x raw (16 chunks/thread) + W packed (12 chunks/thread) ----
#pragma unroll
        for (int u = 0; u < 16; u++) {
            const int cid = tid + 128 * u;       // 0..2047
            const int row = cid >> 4;
            const int off = (cid & 15) * 4;
            cpa16(xs + row * XSR + off, x + (size_t)(rowBase + row) * CC + kk + off);
        }
#pragma unroll
        for (int u = 0; u < 6; u++) {
            const int cid = tid + 128 * u;       // 0..767
            const int row = cid / 24;
            const int off = (cid % 24) * 4;
            cpa16(wph + row * WST + off, g_wh + (kk / 2 + row) * 192 + cb * 96 + off);
            cpa16(wpl + row * WST + off, g_wl + (kk / 2 + row) * 192 + cb * 96 + off);
        }
        asm volatile("cp.async.commit_group;" ::: "memory");
        asm volatile("cp.async.wait_group 0;" ::: "memory");
        __syncthreads();

#pragma unroll
        for (int c = 0; c < 4; c++) {
            // A fragments: inline split from raw x
            unsigned ah[2][4], al[2][4];
#pragma unroll
            for (int mt = 0; mt < 2; mt++) {
                const int rb0 = warp * 32 + mt * 16 + lg;
                const int k0  = 16 * c + 2 * lr;
                float2 p0 = *(float2*)&xs[rb0 * XSR + k0];
                float2 p1 = *(float2*)&xs[(rb0 + 8) * XSR + k0];
                float2 p2 = *(float2*)&xs[rb0 * XSR + k0 + 8];
                float2 p3 = *(float2*)&xs[(rb0 + 8) * XSR + k0 + 8];
                split2(p0.x, p0.y, ah[mt][0], al[mt][0]);
                split2(p1.x, p1.y, ah[mt][1], al[mt][1]);
                split2(p2.x, p2.y, ah[mt][2], al[mt][2]);
                split2(p3.x, p3.y, ah[mt][3], al[mt][3]);
            }
#pragma unroll
            for (int j = 0; j < 12; j++) {
                const unsigned bh0 = __float_as_uint(wph[(8 * c + lr) * WST + j * 8 + lg]);
                const unsigned bh1 = __float_as_uint(wph[(8 * c + lr + 4) * WST + j * 8 + lg]);
                const unsigned bl0 = __float_as_uint(wpl[(8 * c + lr) * WST + j * 8 + lg]);
                const unsigned bl1 = __float_as_uint(wpl[(8 * c + lr + 4) * WST + j * 8 + lg]);
#pragma unroll
                for (int mt = 0; mt < 2; mt++) {
                    mma16(acc[mt][j], ah[mt], bh0, bh1);
                    mma16(acc[mt][j], al[mt], bh0, bh1);
                    mma16(acc[mt][j], ah[mt], bl0, bl1);
                }
            }
        }
        __syncthreads();
    }

    // ---- epilogue: q(fp32) / k(packed [dp][t]) / v(packed [tp][d]) ----
#pragma unroll
    for (int mt = 0; mt < 2; mt++) {
        const int r0 = rowBase + warp * 32 + mt * 16 + lg;
        const int b  = r0 >> 11;
        const int t  = r0 & 2047;
#pragma unroll
        for (int j = 0; j < 12; j++) {
            const int gc = cb * 96 + j * 8 + 2 * lr;
            float4 a = acc[mt][j];
            if (gc < 64) {
                *(float2*)&g_q[r0 * DD + gc]       = make_float2(a.x, a.y);
                *(float2*)&g_q[(r0 + 8) * DD + gc] = make_float2(a.z, a.w);
            } else if (gc < 128) {
                const int dp = (gc - 64) >> 1;
                unsigned h, l;
                split2(a.x, a.y, h, l);
                g_kh[((size_t)b * 32 + dp) * 2048 + t] = h;
                g_kl[((size_t)b * 32 + dp) * 2048 + t] = l;
                split2(a.z, a.w, h, l);
                g_kh[((size_t)b * 32 + dp) * 2048 + t + 8] = h;
                g_kl[((size_t)b * 32 + dp) * 2048 + t + 8] = l;
            } else {
                const int d = gc - 128;
                float ox = __shfl_xor_sync(0xffffffffu, a.x, 4);
                float oy = __shfl_xor_sync(0xffffffffu, a.y, 4);
                float oz = __shfl_xor_sync(0xffffffffu, a.z, 4);
                float ow = __shfl_xor_sync(0xffffffffu, a.w, 4);
                if ((lg & 1) == 0) {
                    unsigned h0, l0, h1, l1;
                    const int sp0 = r0 >> 1;
                    split2(a.x, ox, h0, l0);
                    split2(a.y, oy, h1, l1);
                    *(uint2*)&g_vh[(size_t)sp0 * DD + d] = make_uint2(h0, h1);
                    *(uint2*)&g_vl[(size_t)sp0 * DD + d] = make_uint2(l0, l1);
                    const int sp1 = (r0 + 8) >> 1;
                    split2(a.z, oz, h0, l0);
                    split2(a.w, ow, h1, l1);
                    *(uint2*)&g_vh[(size_t)sp1 * DD + d] = make_uint2(h0, h1);
                    *(uint2*)&g_vl[(size_t)sp1 * DD + d] = make_uint2(l0, l1);
                }
            }
        }
    }
}

// ---------------------------------------------------------------------------
// Kernel 2: flash attention, bf16 3-term mma, pre-split K/V, cp.async
// double-buffered. Br=64 (4 warps), Bc=64, 128 threads.
// exp-trick: m starts at -1e30 so exp() needs no -inf guards.
// ---------------------------------------------------------------------------
#define KVS 72
#define ARR (32 * KVS)
#define ATTN_SMEM (2 * 4 * ARR * 4)

__global__ __launch_bounds__(128, 3) void attn_kernel(float* __restrict__ out)
{
    extern __shared__ float sm[];

    const int b    = blockIdx.y;
    const int qt   = 31 - blockIdx.x;
    const int tid  = threadIdx.x;
    const int lane = tid & 31, warp = tid >> 5;
    const int lg = lane >> 2, lr = lane & 3;
    const int rowg = b * TT + qt * 64;
    const int wrow = warp * 16;

    const unsigned* gkh = g_kh + (size_t)b * 32 * 2048;
    const unsigned* gkl = g_kl + (size_t)b * 32 * 2048;
    const unsigned* gvh = g_vh + (size_t)b * 1024 * DD;
    const unsigned* gvl = g_vl + (size_t)b * 1024 * DD;

    const float NEG_INF = -CUDART_INF_F;

    auto stage = [&](int buf, int st) {
        float* kh = sm + (buf * 4 + 0) * ARR;
        float* kl = sm + (buf * 4 + 1) * ARR;
        float* vh = sm + (buf * 4 + 2) * ARR;
        float* vl = sm + (buf * 4 + 3) * ARR;
#pragma unroll
        for (int u = 0; u < 4; u++) {
            const int cid = tid + 128 * u;
            const int row = cid >> 4;
            const int off = (cid & 15) * 4;
            cpa16(kh + row * KVS + off, gkh + row * 2048 + st * 64 + off);
            cpa16(kl + row * KVS + off, gkl + row * 2048 + st * 64 + off);
            cpa16(vh + row * KVS + off, gvh + (st * 32 + row) * DD + off);
            cpa16(vl + row * KVS + off, gvl + (st * 32 + row) * DD + off);
        }
        asm volatile("cp.async.commit_group;" ::: "memory");
    };

    // ---- Q fragments (prescaled by 1/8, bf16 hi/lo split) ----
    unsigned qh[4][4], ql[4][4];
    {
        const float* q1 = g_q + (rowg + wrow + lg) * DD;
        const float* q2 = q1 + 8 * DD;
#pragma unroll
        for (int c = 0; c < 4; c++) {
            const int cc = 16 * c + 2 * lr;
            float2 a  = *(const float2*)(q1 + cc);
            float2 bq = *(const float2*)(q2 + cc);
            float2 a8 = *(const float2*)(q1 + cc + 8);
            float2 b8 = *(const float2*)(q2 + cc + 8);
            split2(a.x  * 0.125f, a.y  * 0.125f, qh[c][0], ql[c][0]);
            split2(bq.x * 0.125f, bq.y * 0.125f, qh[c][1], ql[c][1]);
            split2(a8.x * 0.125f, a8.y * 0.125f, qh[c][2], ql[c][2]);
            split2(b8.x * 0.125f, b8.y * 0.125f, qh[c][3], ql[c][3]);
        }
    }

    float4 oc[8];
#pragma unroll
    for (int j = 0; j < 8; j++) oc[j] = make_float4(0.f, 0.f, 0.f, 0.f);
    float m1 = -1e30f, m2 = -1e30f, l1 = 0.f, l2 = 0.f;

    const int grow1 = qt * 64 + wrow + lg;
    const int grow2 = grow1 + 8;

    stage(0, 0);
    int buf = 0;

    for (int st = 0; st <= qt; st++) {
        asm volatile("cp.async.wait_group 0;" ::: "memory");
        __syncthreads();
        if (st < qt) stage(buf ^ 1, st + 1);

        const float* khb = sm + (buf * 4 + 0) * ARR;
        const float* klb = sm + (buf * 4 + 1) * ARR;
        const float* vhb = sm + (buf * 4 + 2) * ARR;
        const float* vlb = sm + (buf * 4 + 3) * ARR;

        // ---- S = Q K^T (3-term bf16) ----
        float4 sc[8];
#pragma unroll
        for (int j = 0; j < 8; j++) sc[j] = make_float4(0.f, 0.f, 0.f, 0.f);
#pragma unroll
        for (int c = 0; c < 4; c++) {
            const int ra = (8 * c + lr) * KVS + lg;
            const int rb = (8 * c + lr + 4) * KVS + lg;
#pragma unroll
            for (int j = 0; j < 8; j++) {
                const unsigned kh0 = __float_as_uint(khb[ra + j * 8]);
                const unsigned kh1 = __float_as_uint(khb[rb + j * 8]);
                const unsigned kl0 = __float_as_uint(klb[ra + j * 8]);
                const unsigned kl1 = __float_as_uint(klb[rb + j * 8]);
                mma16(sc[j], qh[c], kh0, kh1);
                mma16(sc[j], ql[c], kh0, kh1);
                mma16(sc[j], qh[c], kl0, kl1);
            }
        }

        // ---- mask (diag hoisted; zero-quirk always) ----
        if (st == qt) {
            const int cbv = st * 64 + 2 * lr;
#pragma unroll
            for (int j = 0; j < 8; j++) {
                const int c0g = cbv + 8 * j;
                if (c0g     > grow1 || sc[j].x == 0.0f) sc[j].x = NEG_INF;
                if (c0g + 1 > grow1 || sc[j].y == 0.0f) sc[j].y = NEG_INF;
                if (c0g     > grow2 || sc[j].z == 0.0f) sc[j].z = NEG_INF;
                if (c0g + 1 > grow2 || sc[j].w == 0.0f) sc[j].w = NEG_INF;
            }
        } else {
#pragma unroll
            for (int j = 0; j < 8; j++) {
                if (sc[j].x == 0.0f) sc[j].x = NEG_INF;
                if (sc[j].y == 0.0f) sc[j].y = NEG_INF;
                if (sc[j].z == 0.0f) sc[j].z = NEG_INF;
                if (sc[j].w == 0.0f) sc[j].w = NEG_INF;
            }
        }

        // ---- online softmax (exp(-inf)=0; m finite so no guards) ----
        float rm1 = NEG_INF, rm2 = NEG_INF;
#pragma unroll
        for (int j = 0; j < 8; j++) {
            rm1 = fmaxf(rm1, fmaxf(sc[j].x, sc[j].y));
            rm2 = fmaxf(rm2, fmaxf(sc[j].z, sc[j].w));
        }
        rm1 = fmaxf(rm1, __shfl_xor_sync(0xffffffffu, rm1, 1));
        rm1 = fmaxf(rm1, __shfl_xor_sync(0xffffffffu, rm1, 2));
        rm2 = fmaxf(rm2, __shfl_xor_sync(0xffffffffu, rm2, 1));
        rm2 = fmaxf(rm2, __shfl_xor_sync(0xffffffffu, rm2, 2));

        const float mn1 = fmaxf(m1, rm1);
        const float mn2 = fmaxf(m2, rm2);
        const float fac1 = __expf(m1 - mn1);
        const float fac2 = __expf(m2 - mn2);

        unsigned pha[8], phb[8], pla[8], plb[8];
        float ps1 = 0.f, ps2 = 0.f;
#pragma unroll
        for (int j = 0; j < 8; j++) {
            const float px = __expf(sc[j].x - mn1);
            const float py = __expf(sc[j].y - mn1);
            const float pz = __expf(sc[j].z - mn2);
            const float pw = __expf(sc[j].w - mn2);
            ps1 += px + py;
            ps2 += pz + pw;
            split2(px, py, pha[j], pla[j]);
            split2(pz, pw, phb[j], plb[j]);
        }
        ps1 += __shfl_xor_sync(0xffffffffu, ps1, 1);
        ps1 += __shfl_xor_sync(0xffffffffu, ps1, 2);
        ps2 += __shfl_xor_sync(0xffffffffu, ps2, 1);
        ps2 += __shfl_xor_sync(0xffffffffu, ps2, 2);

        l1 = l1 * fac1 + ps1;  m1 = mn1;
        l2 = l2 * fac2 + ps2;  m2 = mn2;
#pragma unroll
        for (int j = 0; j < 8; j++) {
            oc[j].x *= fac1; oc[j].y *= fac1;
            oc[j].z *= fac2; oc[j].w *= fac2;
        }

        // ---- O += P V (3-term bf16, A-fragments from registers) ----
#pragma unroll
        for (int c = 0; c < 4; c++) {
            const unsigned ah[4] = {pha[2 * c], phb[2 * c], pha[2 * c + 1], phb[2 * c + 1]};
            const unsigned al[4] = {pla[2 * c], plb[2 * c], pla[2 * c + 1], plb[2 * c + 1]};
            const int ra = (8 * c + lr) * KVS + lg;
            const int rb = (8 * c + lr + 4) * KVS + lg;
#pragma unroll
            for (int j = 0; j < 8; j++) {
                const unsigned vh0 = __float_as_uint(vhb[ra + j * 8]);
                const unsigned vh1 = __float_as_uint(vhb[rb + j * 8]);
                const unsigned vl0 = __float_as_uint(vlb[ra + j * 8]);
                const unsigned vl1 = __float_as_uint(vlb[rb + j * 8]);
                mma16(oc[j], ah, vh0, vh1);
                mma16(oc[j], al, vh0, vh1);
                mma16(oc[j], ah, vl0, vl1);
            }
        }
        buf ^= 1;
    }

    // ---- epilogue ----
    const float inv1 = 1.0f / l1;
    const float inv2 = 1.0f / l2;
    const int ob1 = (rowg + wrow + lg) * DD + 2 * lr;
    const int ob2 = ob1 + 8 * DD;
#pragma unroll
    for (int j = 0; j < 8; j++) {
        *(float2*)&out[ob1 + 8 * j] = make_float2(oc[j].x * inv1, oc[j].y * inv1);
        *(float2*)&out[ob2 + 8 * j] = make_float2(oc[j].z * inv2, oc[j].w * inv2);
    }
}

// ---------------------------------------------------------------------------
extern "C" void kernel_launch(void* const* d_in, const int* in_sizes, int n_in,
                              void* d_out, int out_size)
{
    (void)in_sizes; (void)n_in; (void)out_size;
    const float* x  = (const float*)d_in[0];
    const float* Wq = (const float*)d_in[1];
    const float* Wk = (const float*)d_in[2];
    const float* Wv = (const float*)d_in[3];
    float* out = (float*)d_out;

    cudaFuncSetAttribute(proj_kernel,
                         cudaFuncAttributeMaxDynamicSharedMemorySize, PROJ_SMEM);
    cudaFuncSetAttribute(attn_kernel,
                         cudaFuncAttributeMaxDynamicSharedMemorySize, ATTN_SMEM);

    wsplit_kernel<<<192, 192>>>(Wq, Wk, Wv);
    proj_kernel<<<dim3(BB * TT / 128, 2), 128, PROJ_SMEM>>>(x);
    attn_kernel<<<dim3(32, BB), 128, ATTN_SMEM>>>(out);
}

// round 7
// speedup vs baseline: 3.6748x; 1.0418x over previous
#include <cuda_runtime.h>
#include <math_constants.h>

#define BB 16
#define TT 2048
#define CC 384
#define DD 64

// q fp32; k/v pre-split packed bf16x2 hi/lo in attn-ready layouts
__device__ float    g_q[BB * TT * DD];
__device__ unsigned g_kh[BB * 32 * TT];        // [b][dp][t]
__device__ unsigned g_kl[BB * 32 * TT];
__device__ unsigned g_vh[BB * (TT / 2) * DD];  // [b][tp][d]
__device__ unsigned g_vl[BB * (TT / 2) * DD];
// fused W pre-split: [kp 0..191][n 0..191] (n: 0-63 Wq, 64-127 Wk, 128-191 Wv)
__device__ unsigned g_wh[192 * 192];
__device__ unsigned g_wl[192 * 192];

// ---- helpers ------------------------------------------------------------
__device__ __forceinline__ void split2(float a, float b, unsigned& hi, unsigned& lo) {
    unsigned h;
    asm("cvt.rn.bf16x2.f32 %0, %1, %2;" : "=r"(h) : "f"(b), "f"(a));
    float ha = __uint_as_float(h << 16);
    float hb = __uint_as_float(h & 0xffff0000u);
    unsigned l;
    asm("cvt.rn.bf16x2.f32 %0, %1, %2;" : "=r"(l) : "f"(b - hb), "f"(a - ha));
    hi = h; lo = l;
}
__device__ __forceinline__ void mma16(float4& c, const unsigned a[4],
                                      unsigned b0, unsigned b1) {
    asm("mma.sync.aligned.m16n8k16.row.col.f32.bf16.bf16.f32 "
        "{%0,%1,%2,%3},{%4,%5,%6,%7},{%8,%9},{%0,%1,%2,%3};"
        : "+f"(c.x), "+f"(c.y), "+f"(c.z), "+f"(c.w)
        : "r"(a[0]), "r"(a[1]), "r"(a[2]), "r"(a[3]), "r"(b0), "r"(b1));
}
__device__ __forceinline__ void cpa16(const void* smem_dst, const void* gsrc) {
    unsigned d = (unsigned)__cvta_generic_to_shared(smem_dst);
    asm volatile("cp.async.cg.shared.global [%0], [%1], 16;" :: "r"(d), "l"(gsrc));
}
__device__ __forceinline__ float ex2(float x) {
    float r;
    asm("ex2.approx.f32 %0, %1;" : "=f"(r) : "f"(x));
    return r;
}

// ---------------------------------------------------------------------------
// Kernel 0: one-shot W split. 192 blocks x 192 threads.
// ---------------------------------------------------------------------------
__global__ void wsplit_kernel(const float* __restrict__ Wq,
                              const float* __restrict__ Wk,
                              const float* __restrict__ Wv)
{
    const int kp = blockIdx.x;
    const int n  = threadIdx.x;
    const float* W = (n < 64) ? Wq : (n < 128) ? Wk : Wv;
    const int c = n & 63;
    unsigned h, l;
    split2(W[(2 * kp) * DD + c], W[(2 * kp + 1) * DD + c], h, l);
    g_wh[kp * 192 + n] = h;
    g_wl[kp * 192 + n] = l;
}

// ---------------------------------------------------------------------------
// Kernel 1: fused QKV projection, bf16 3-term mma.
// grid (256 row-blocks of 128, 2 col-blocks of 96). 128 threads, 4 warps.
// ---------------------------------------------------------------------------
#define XSR 68
#define WST 100
#define PROJ_SMEM ((128 * XSR + 2 * 32 * WST) * 4)

__global__ __launch_bounds__(128, 3) void proj_kernel(const float* __restrict__ x)
{
    extern __shared__ float psm[];
    float* xs  = psm;
    float* wph = xs + 128 * XSR;
    float* wpl = wph + 32 * WST;

    const int tid  = threadIdx.x;
    const int lane = tid & 31, warp = tid >> 5;
    const int lg = lane >> 2, lr = lane & 3;
    const int rowBase = blockIdx.x * 128;
    const int cb = blockIdx.y;

    float4 acc[2][12];
#pragma unroll
    for (int mt = 0; mt < 2; mt++)
#pragma unroll
        for (int j = 0; j < 12; j++) acc[mt][j] = make_float4(0.f, 0.f, 0.f, 0.f);

    for (int kk = 0; kk < CC; kk += 64) {
#pragma unroll
        for (int u = 0; u < 16; u++) {
            const int cid = tid + 128 * u;
            const int row = cid >> 4;
            const int off = (cid & 15) * 4;
            cpa16(xs + row * XSR + off, x + (size_t)(rowBase + row) * CC + kk + off);
        }
#pragma unroll
        for (int u = 0; u < 6; u++) {
            const int cid = tid + 128 * u;
            const int row = cid / 24;
            const int off = (cid % 24) * 4;
            cpa16(wph + row * WST + off, g_wh + (kk / 2 + row) * 192 + cb * 96 + off);
            cpa16(wpl + row * WST + off, g_wl + (kk / 2 + row) * 192 + cb * 96 + off);
        }
        asm volatile("cp.async.commit_group;" ::: "memory");
        asm volatile("cp.async.wait_group 0;" ::: "memory");
        __syncthreads();

#pragma unroll
        for (int c = 0; c < 4; c++) {
            unsigned ah[2][4], al[2][4];
#pragma unroll
            for (int mt = 0; mt < 2; mt++) {
                const int rb0 = warp * 32 + mt * 16 + lg;
                const int k0  = 16 * c + 2 * lr;
                float2 p0 = *(float2*)&xs[rb0 * XSR + k0];
                float2 p1 = *(float2*)&xs[(rb0 + 8) * XSR + k0];
                float2 p2 = *(float2*)&xs[rb0 * XSR + k0 + 8];
                float2 p3 = *(float2*)&xs[(rb0 + 8) * XSR + k0 + 8];
                split2(p0.x, p0.y, ah[mt][0], al[mt][0]);
                split2(p1.x, p1.y, ah[mt][1], al[mt][1]);
                split2(p2.x, p2.y, ah[mt][2], al[mt][2]);
                split2(p3.x, p3.y, ah[mt][3], al[mt][3]);
            }
#pragma unroll
            for (int j = 0; j < 12; j++) {
                const unsigned bh0 = __float_as_uint(wph[(8 * c + lr) * WST + j * 8 + lg]);
                const unsigned bh1 = __float_as_uint(wph[(8 * c + lr + 4) * WST + j * 8 + lg]);
                const unsigned bl0 = __float_as_uint(wpl[(8 * c + lr) * WST + j * 8 + lg]);
                const unsigned bl1 = __float_as_uint(wpl[(8 * c + lr + 4) * WST + j * 8 + lg]);
#pragma unroll
                for (int mt = 0; mt < 2; mt++) {
                    mma16(acc[mt][j], ah[mt], bh0, bh1);
                    mma16(acc[mt][j], al[mt], bh0, bh1);
                    mma16(acc[mt][j], ah[mt], bl0, bl1);
                }
            }
        }
        __syncthreads();
    }

#pragma unroll
    for (int mt = 0; mt < 2; mt++) {
        const int r0 = rowBase + warp * 32 + mt * 16 + lg;
        const int b  = r0 >> 11;
        const int t  = r0 & 2047;
#pragma unroll
        for (int j = 0; j < 12; j++) {
            const int gc = cb * 96 + j * 8 + 2 * lr;
            float4 a = acc[mt][j];
            if (gc < 64) {
                *(float2*)&g_q[r0 * DD + gc]       = make_float2(a.x, a.y);
                *(float2*)&g_q[(r0 + 8) * DD + gc] = make_float2(a.z, a.w);
            } else if (gc < 128) {
                const int dp = (gc - 64) >> 1;
                unsigned h, l;
                split2(a.x, a.y, h, l);
                g_kh[((size_t)b * 32 + dp) * 2048 + t] = h;
                g_kl[((size_t)b * 32 + dp) * 2048 + t] = l;
                split2(a.z, a.w, h, l);
                g_kh[((size_t)b * 32 + dp) * 2048 + t + 8] = h;
                g_kl[((size_t)b * 32 + dp) * 2048 + t + 8] = l;
            } else {
                const int d = gc - 128;
                float ox = __shfl_xor_sync(0xffffffffu, a.x, 4);
                float oy = __shfl_xor_sync(0xffffffffu, a.y, 4);
                float oz = __shfl_xor_sync(0xffffffffu, a.z, 4);
                float ow = __shfl_xor_sync(0xffffffffu, a.w, 4);
                if ((lg & 1) == 0) {
                    unsigned h0, l0, h1, l1;
                    const int sp0 = r0 >> 1;
                    split2(a.x, ox, h0, l0);
                    split2(a.y, oy, h1, l1);
                    *(uint2*)&g_vh[(size_t)sp0 * DD + d] = make_uint2(h0, h1);
                    *(uint2*)&g_vl[(size_t)sp0 * DD + d] = make_uint2(l0, l1);
                    const int sp1 = (r0 + 8) >> 1;
                    split2(a.z, oz, h0, l0);
                    split2(a.w, ow, h1, l1);
                    *(uint2*)&g_vh[(size_t)sp1 * DD + d] = make_uint2(h0, h1);
                    *(uint2*)&g_vl[(size_t)sp1 * DD + d] = make_uint2(l0, l1);
                }
            }
        }
    }
}

// ---------------------------------------------------------------------------
// Kernel 2: flash attention, bf16 3-term mma, triangle-balanced.
// Each CTA processes q-tiles (31-bx) then (bx): constant 33 tile-iters.
// Br=64 (4 warps), Bc=64, 128 threads, cp.async double-buffered.
// Scores computed in log2 domain (log2e folded into q prescale).
// ---------------------------------------------------------------------------
#define KVS 72
#define ARR (32 * KVS)
#define ATTN_SMEM (2 * 4 * ARR * 4)

__global__ __launch_bounds__(128, 3) void attn_kernel(float* __restrict__ out)
{
    extern __shared__ float sm[];

    const int b    = blockIdx.y;
    const int tid  = threadIdx.x;
    const int lane = tid & 31, warp = tid >> 5;
    const int lg = lane >> 2, lr = lane & 3;
    const int wrow = warp * 16;

    const unsigned* gkh = g_kh + (size_t)b * 32 * 2048;
    const unsigned* gkl = g_kl + (size_t)b * 32 * 2048;
    const unsigned* gvh = g_vh + (size_t)b * 1024 * DD;
    const unsigned* gvl = g_vl + (size_t)b * 1024 * DD;

    const float NEG_INF = -CUDART_INF_F;
    const float SCL = 0.125f * 1.44269504088896340736f;  // (1/sqrt(64)) * log2(e)

    auto stage = [&](int buf, int st) {
        float* kh = sm + (buf * 4 + 0) * ARR;
        float* kl = sm + (buf * 4 + 1) * ARR;
        float* vh = sm + (buf * 4 + 2) * ARR;
        float* vl = sm + (buf * 4 + 3) * ARR;
#pragma unroll
        for (int u = 0; u < 4; u++) {
            const int cid = tid + 128 * u;
            const int row = cid >> 4;
            const int off = (cid & 15) * 4;
            cpa16(kh + row * KVS + off, gkh + row * 2048 + st * 64 + off);
            cpa16(kl + row * KVS + off, gkl + row * 2048 + st * 64 + off);
            cpa16(vh + row * KVS + off, gvh + (st * 32 + row) * DD + off);
            cpa16(vl + row * KVS + off, gvl + (st * 32 + row) * DD + off);
        }
        asm volatile("cp.async.commit_group;" ::: "memory");
    };

    for (int half = 0; half < 2; half++) {
        const int qt = half ? blockIdx.x : 31 - blockIdx.x;
        const int rowg = b * TT + qt * 64;
        const int grow1 = qt * 64 + wrow + lg;
        const int grow2 = grow1 + 8;

        // ---- Q fragments (prescaled by SCL, bf16 hi/lo split) ----
        unsigned qh[4][4], ql[4][4];
        {
            const float* q1 = g_q + (rowg + wrow + lg) * DD;
            const float* q2 = q1 + 8 * DD;
#pragma unroll
            for (int c = 0; c < 4; c++) {
                const int cc = 16 * c + 2 * lr;
                float2 a  = *(const float2*)(q1 + cc);
                float2 bq = *(const float2*)(q2 + cc);
                float2 a8 = *(const float2*)(q1 + cc + 8);
                float2 b8 = *(const float2*)(q2 + cc + 8);
                split2(a.x  * SCL, a.y  * SCL, qh[c][0], ql[c][0]);
                split2(bq.x * SCL, bq.y * SCL, qh[c][1], ql[c][1]);
                split2(a8.x * SCL, a8.y * SCL, qh[c][2], ql[c][2]);
                split2(b8.x * SCL, b8.y * SCL, qh[c][3], ql[c][3]);
            }
        }

        float4 oc[8];
#pragma unroll
        for (int j = 0; j < 8; j++) oc[j] = make_float4(0.f, 0.f, 0.f, 0.f);
        float m1 = -1e30f, m2 = -1e30f, l1 = 0.f, l2 = 0.f;

        __syncthreads();          // protect smem reuse across halves
        stage(0, 0);
        int buf = 0;

        for (int st = 0; st <= qt; st++) {
            asm volatile("cp.async.wait_group 0;" ::: "memory");
            __syncthreads();
            if (st < qt) stage(buf ^ 1, st + 1);

            const float* khb = sm + (buf * 4 + 0) * ARR;
            const float* klb = sm + (buf * 4 + 1) * ARR;
            const float* vhb = sm + (buf * 4 + 2) * ARR;
            const float* vlb = sm + (buf * 4 + 3) * ARR;

            // ---- S = Q K^T (3-term bf16), log2 domain ----
            float4 sc[8];
#pragma unroll
            for (int j = 0; j < 8; j++) sc[j] = make_float4(0.f, 0.f, 0.f, 0.f);
#pragma unroll
            for (int c = 0; c < 4; c++) {
                const int ra = (8 * c + lr) * KVS + lg;
                const int rb = (8 * c + lr + 4) * KVS + lg;
#pragma unroll
                for (int j = 0; j < 8; j++) {
                    const unsigned kh0 = __float_as_uint(khb[ra + j * 8]);
                    const unsigned kh1 = __float_as_uint(khb[rb + j * 8]);
                    const unsigned kl0 = __float_as_uint(klb[ra + j * 8]);
                    const unsigned kl1 = __float_as_uint(klb[rb + j * 8]);
                    mma16(sc[j], qh[c], kh0, kh1);
                    mma16(sc[j], ql[c], kh0, kh1);
                    mma16(sc[j], qh[c], kl0, kl1);
                }
            }

            // ---- mask (diag hoisted; zero-quirk always) ----
            if (st == qt) {
                const int cbv = st * 64 + 2 * lr;
#pragma unroll
                for (int j = 0; j < 8; j++) {
                    const int c0g = cbv + 8 * j;
                    if (c0g     > grow1 || sc[j].x == 0.0f) sc[j].x = NEG_INF;
                    if (c0g + 1 > grow1 || sc[j].y == 0.0f) sc[j].y = NEG_INF;
                    if (c0g     > grow2 || sc[j].z == 0.0f) sc[j].z = NEG_INF;
                    if (c0g + 1 > grow2 || sc[j].w == 0.0f) sc[j].w = NEG_INF;
                }
            } else {
#pragma unroll
                for (int j = 0; j < 8; j++) {
                    if (sc[j].x == 0.0f) sc[j].x = NEG_INF;
                    if (sc[j].y == 0.0f) sc[j].y = NEG_INF;
                    if (sc[j].z == 0.0f) sc[j].z = NEG_INF;
                    if (sc[j].w == 0.0f) sc[j].w = NEG_INF;
                }
            }

            // ---- online softmax (exp2; m finite so no guards) ----
            float rm1 = NEG_INF, rm2 = NEG_INF;
#pragma unroll
            for (int j = 0; j < 8; j++) {
                rm1 = fmaxf(rm1, fmaxf(sc[j].x, sc[j].y));
                rm2 = fmaxf(rm2, fmaxf(sc[j].z, sc[j].w));
            }
            rm1 = fmaxf(rm1, __shfl_xor_sync(0xffffffffu, rm1, 1));
            rm1 = fmaxf(rm1, __shfl_xor_sync(0xffffffffu, rm1, 2));
            rm2 = fmaxf(rm2, __shfl_xor_sync(0xffffffffu, rm2, 1));
            rm2 = fmaxf(rm2, __shfl_xor_sync(0xffffffffu, rm2, 2));

            const float mn1 = fmaxf(m1, rm1);
            const float mn2 = fmaxf(m2, rm2);
            const float fac1 = ex2(m1 - mn1);
            const float fac2 = ex2(m2 - mn2);

            unsigned pha[8], phb[8], pla[8], plb[8];
            float ps1 = 0.f, ps2 = 0.f;
#pragma unroll
            for (int j = 0; j < 8; j++) {
                const float px = ex2(sc[j].x - mn1);
                const float py = ex2(sc[j].y - mn1);
                const float pz = ex2(sc[j].z - mn2);
                const float pw = ex2(sc[j].w - mn2);
                ps1 += px + py;
                ps2 += pz + pw;
                split2(px, py, pha[j], pla[j]);
                split2(pz, pw, phb[j], plb[j]);
            }
            ps1 += __shfl_xor_sync(0xffffffffu, ps1, 1);
            ps1 += __shfl_xor_sync(0xffffffffu, ps1, 2);
            ps2 += __shfl_xor_sync(0xffffffffu, ps2, 1);
            ps2 += __shfl_xor_sync(0xffffffffu, ps2, 2);

            l1 = l1 * fac1 + ps1;  m1 = mn1;
            l2 = l2 * fac2 + ps2;  m2 = mn2;
#pragma unroll
            for (int j = 0; j < 8; j++) {
                oc[j].x *= fac1; oc[j].y *= fac1;
                oc[j].z *= fac2; oc[j].w *= fac2;
            }

            // ---- O += P V (3-term bf16, A-fragments from registers) ----
#pragma unroll
            for (int c = 0; c < 4; c++) {
                const unsigned ah[4] = {pha[2 * c], phb[2 * c], pha[2 * c + 1], phb[2 * c + 1]};
                const unsigned al[4] = {pla[2 * c], plb[2 * c], pla[2 * c + 1], plb[2 * c + 1]};
                const int ra = (8 * c + lr) * KVS + lg;
                const int rb = (8 * c + lr + 4) * KVS + lg;
#pragma unroll
                for (int j = 0; j < 8; j++) {
                    const unsigned vh0 = __float_as_uint(vhb[ra + j * 8]);
                    const unsigned vh1 = __float_as_uint(vhb[rb + j * 8]);
                    const unsigned vl0 = __float_as_uint(vlb[ra + j * 8]);
                    const unsigned vl1 = __float_as_uint(vlb[rb + j * 8]);
                    mma16(oc[j], ah, vh0, vh1);
                    mma16(oc[j], al, vh0, vh1);
                    mma16(oc[j], ah, vl0, vl1);
                }
            }
            buf ^= 1;
        }

        // ---- epilogue ----
        const float inv1 = 1.0f / l1;
        const float inv2 = 1.0f / l2;
        const int ob1 = (rowg + wrow + lg) * DD + 2 * lr;
        const int ob2 = ob1 + 8 * DD;
#pragma unroll
        for (int j = 0; j < 8; j++) {
            *(float2*)&out[ob1 + 8 * j] = make_float2(oc[j].x * inv1, oc[j].y * inv1);
            *(float2*)&out[ob2 + 8 * j] = make_float2(oc[j].z * inv2, oc[j].w * inv2);
        }
    }
}

// ---------------------------------------------------------------------------
extern "C" void kernel_launch(void* const* d_in, const int* in_sizes, int n_in,
                              void* d_out, int out_size)
{
    (void)in_sizes; (void)n_in; (void)out_size;
    const float* x  = (const float*)d_in[0];
    const float* Wq = (const float*)d_in[1];
    const float* Wk = (const float*)d_in[2];
    const float* Wv = (const float*)d_in[3];
    float* out = (float*)d_out;

    cudaFuncSetAttribute(proj_kernel,
                         cudaFuncAttributeMaxDynamicSharedMemorySize, PROJ_SMEM);
    cudaFuncSetAttribute(attn_kernel,
                         cudaFuncAttributeMaxDynamicSharedMemorySize, ATTN_SMEM);

    wsplit_kernel<<<192, 192>>>(Wq, Wk, Wv);
    proj_kernel<<<dim3(BB * TT / 128, 2), 128, PROJ_SMEM>>>(x);
    attn_kernel<<<dim3(16, BB), 128, ATTN_SMEM>>>(out);
}

// round 8
// speedup vs baseline: 4.0735x; 1.1085x over previous
#include <cuda_runtime.h>
#include <cuda_fp16.h>
#include <math_constants.h>

#define BB 16
#define TT 2048
#define CC 384
#define DD 64

// q fp32; k pre-split packed bf16x2 hi/lo; v packed fp16x2 (single precision)
__device__ float    g_q[BB * TT * DD];
__device__ unsigned g_kh[BB * 32 * TT];        // [b][dp][t]
__device__ unsigned g_kl[BB * 32 * TT];
__device__ unsigned g_vf[BB * (TT / 2) * DD];  // [b][tp][d] fp16x2 pack(v[2tp][d], v[2tp+1][d])
// fused W pre-split: [kp 0..191][n 0..191] (n: 0-63 Wq, 64-127 Wk, 128-191 Wv)
__device__ unsigned g_wh[192 * 192];
__device__ unsigned g_wl[192 * 192];

// ---- helpers ------------------------------------------------------------
__device__ __forceinline__ void split2(float a, float b, unsigned& hi, unsigned& lo) {
    unsigned h;
    asm("cvt.rn.bf16x2.f32 %0, %1, %2;" : "=r"(h) : "f"(b), "f"(a));
    float ha = __uint_as_float(h << 16);
    float hb = __uint_as_float(h & 0xffff0000u);
    unsigned l;
    asm("cvt.rn.bf16x2.f32 %0, %1, %2;" : "=r"(l) : "f"(b - hb), "f"(a - ha));
    hi = h; lo = l;
}
__device__ __forceinline__ unsigned packh2(float a, float b) {
    unsigned r;
    asm("cvt.rn.f16x2.f32 %0, %1, %2;" : "=r"(r) : "f"(b), "f"(a));
    return r;
}
__device__ __forceinline__ void splith2(float a, float b, unsigned& hi, unsigned& lo) {
    unsigned h;
    asm("cvt.rn.f16x2.f32 %0, %1, %2;" : "=r"(h) : "f"(b), "f"(a));
    __half2 hh = *reinterpret_cast<__half2*>(&h);
    float2 hf = __half22float2(hh);
    unsigned l;
    asm("cvt.rn.f16x2.f32 %0, %1, %2;" : "=r"(l) : "f"(b - hf.y), "f"(a - hf.x));
    hi = h; lo = l;
}
__device__ __forceinline__ void mma16(float4& c, const unsigned a[4],
                                      unsigned b0, unsigned b1) {
    asm("mma.sync.aligned.m16n8k16.row.col.f32.bf16.bf16.f32 "
        "{%0,%1,%2,%3},{%4,%5,%6,%7},{%8,%9},{%0,%1,%2,%3};"
        : "+f"(c.x), "+f"(c.y), "+f"(c.z), "+f"(c.w)
        : "r"(a[0]), "r"(a[1]), "r"(a[2]), "r"(a[3]), "r"(b0), "r"(b1));
}
__device__ __forceinline__ void mma16h(float4& c, const unsigned a[4],
                                       unsigned b0, unsigned b1) {
    asm("mma.sync.aligned.m16n8k16.row.col.f32.f16.f16.f32 "
        "{%0,%1,%2,%3},{%4,%5,%6,%7},{%8,%9},{%0,%1,%2,%3};"
        : "+f"(c.x), "+f"(c.y), "+f"(c.z), "+f"(c.w)
        : "r"(a[0]), "r"(a[1]), "r"(a[2]), "r"(a[3]), "r"(b0), "r"(b1));
}
__device__ __forceinline__ void cpa16(const void* smem_dst, const void* gsrc) {
    unsigned d = (unsigned)__cvta_generic_to_shared(smem_dst);
    asm volatile("cp.async.cg.shared.global [%0], [%1], 16;" :: "r"(d), "l"(gsrc));
}
__device__ __forceinline__ float ex2(float x) {
    float r;
    asm("ex2.approx.f32 %0, %1;" : "=f"(r) : "f"(x));
    return r;
}

// ---------------------------------------------------------------------------
// Kernel 0: one-shot W split. 192 blocks x 192 threads.
// ---------------------------------------------------------------------------
__global__ void wsplit_kernel(const float* __restrict__ Wq,
                              const float* __restrict__ Wk,
                              const float* __restrict__ Wv)
{
    const int kp = blockIdx.x;
    const int n  = threadIdx.x;
    const float* W = (n < 64) ? Wq : (n < 128) ? Wk : Wv;
    const int c = n & 63;
    unsigned h, l;
    split2(W[(2 * kp) * DD + c], W[(2 * kp + 1) * DD + c], h, l);
    g_wh[kp * 192 + n] = h;
    g_wl[kp * 192 + n] = l;
}

// ---------------------------------------------------------------------------
// Kernel 1: fused QKV projection, bf16 3-term mma.
// grid (256 row-blocks of 128, 2 col-blocks of 96). 128 threads, 4 warps.
// ---------------------------------------------------------------------------
#define XSR 68
#define WST 100
#define PROJ_SMEM ((128 * XSR + 2 * 32 * WST) * 4)

__global__ __launch_bounds__(128, 3) void proj_kernel(const float* __restrict__ x)
{
    extern __shared__ float psm[];
    float* xs  = psm;
    float* wph = xs + 128 * XSR;
    float* wpl = wph + 32 * WST;

    const int tid  = threadIdx.x;
    const int lane = tid & 31, warp = tid >> 5;
    const int lg = lane >> 2, lr = lane & 3;
    const int rowBase = blockIdx.x * 128;
    const int cb = blockIdx.y;

    float4 acc[2][12];
#pragma unroll
    for (int mt = 0; mt < 2; mt++)
#pragma unroll
        for (int j = 0; j < 12; j++) acc[mt][j] = make_float4(0.f, 0.f, 0.f, 0.f);

    for (int kk = 0; kk < CC; kk += 64) {
#pragma unroll
        for (int u = 0; u < 16; u++) {
            const int cid = tid + 128 * u;
            const int row = cid >> 4;
            const int off = (cid & 15) * 4;
            cpa16(xs + row * XSR + off, x + (size_t)(rowBase + row) * CC + kk + off);
        }
#pragma unroll
        for (int u = 0; u < 6; u++) {
            const int cid = tid + 128 * u;
            const int row = cid / 24;
            const int off = (cid % 24) * 4;
            cpa16(wph + row * WST + off, g_wh + (kk / 2 + row) * 192 + cb * 96 + off);
            cpa16(wpl + row * WST + off, g_wl + (kk / 2 + row) * 192 + cb * 96 + off);
        }
        asm volatile("cp.async.commit_group;" ::: "memory");
        asm volatile("cp.async.wait_group 0;" ::: "memory");
        __syncthreads();

#pragma unroll
        for (int c = 0; c < 4; c++) {
            unsigned ah[2][4], al[2][4];
#pragma unroll
            for (int mt = 0; mt < 2; mt++) {
                const int rb0 = warp * 32 + mt * 16 + lg;
                const int k0  = 16 * c + 2 * lr;
                float2 p0 = *(float2*)&xs[rb0 * XSR + k0];
                float2 p1 = *(float2*)&xs[(rb0 + 8) * XSR + k0];
                float2 p2 = *(float2*)&xs[rb0 * XSR + k0 + 8];
                float2 p3 = *(float2*)&xs[(rb0 + 8) * XSR + k0 + 8];
                split2(p0.x, p0.y, ah[mt][0], al[mt][0]);
                split2(p1.x, p1.y, ah[mt][1], al[mt][1]);
                split2(p2.x, p2.y, ah[mt][2], al[mt][2]);
                split2(p3.x, p3.y, ah[mt][3], al[mt][3]);
            }
#pragma unroll
            for (int j = 0; j < 12; j++) {
                const unsigned bh0 = __float_as_uint(wph[(8 * c + lr) * WST + j * 8 + lg]);
                const unsigned bh1 = __float_as_uint(wph[(8 * c + lr + 4) * WST + j * 8 + lg]);
                const unsigned bl0 = __float_as_uint(wpl[(8 * c + lr) * WST + j * 8 + lg]);
                const unsigned bl1 = __float_as_uint(wpl[(8 * c + lr + 4) * WST + j * 8 + lg]);
#pragma unroll
                for (int mt = 0; mt < 2; mt++) {
                    mma16(acc[mt][j], ah[mt], bh0, bh1);
                    mma16(acc[mt][j], al[mt], bh0, bh1);
                    mma16(acc[mt][j], ah[mt], bl0, bl1);
                }
            }
        }
        __syncthreads();
    }

#pragma unroll
    for (int mt = 0; mt < 2; mt++) {
        const int r0 = rowBase + warp * 32 + mt * 16 + lg;
        const int b  = r0 >> 11;
        const int t  = r0 & 2047;
#pragma unroll
        for (int j = 0; j < 12; j++) {
            const int gc = cb * 96 + j * 8 + 2 * lr;
            float4 a = acc[mt][j];
            if (gc < 64) {
                *(float2*)&g_q[r0 * DD + gc]       = make_float2(a.x, a.y);
                *(float2*)&g_q[(r0 + 8) * DD + gc] = make_float2(a.z, a.w);
            } else if (gc < 128) {
                const int dp = (gc - 64) >> 1;
                unsigned h, l;
                split2(a.x, a.y, h, l);
                g_kh[((size_t)b * 32 + dp) * 2048 + t] = h;
                g_kl[((size_t)b * 32 + dp) * 2048 + t] = l;
                split2(a.z, a.w, h, l);
                g_kh[((size_t)b * 32 + dp) * 2048 + t + 8] = h;
                g_kl[((size_t)b * 32 + dp) * 2048 + t + 8] = l;
            } else {
                const int d = gc - 128;
                float ox = __shfl_xor_sync(0xffffffffu, a.x, 4);
                float oy = __shfl_xor_sync(0xffffffffu, a.y, 4);
                float oz = __shfl_xor_sync(0xffffffffu, a.z, 4);
                float ow = __shfl_xor_sync(0xffffffffu, a.w, 4);
                if ((lg & 1) == 0) {
                    const int sp0 = r0 >> 1;
                    *(uint2*)&g_vf[(size_t)sp0 * DD + d] =
                        make_uint2(packh2(a.x, ox), packh2(a.y, oy));
                    const int sp1 = (r0 + 8) >> 1;
                    *(uint2*)&g_vf[(size_t)sp1 * DD + d] =
                        make_uint2(packh2(a.z, oz), packh2(a.w, ow));
                }
            }
        }
    }
}

// ---------------------------------------------------------------------------
// Kernel 2: flash attention. QK: bf16 3-term. PV: fp16 (P hi/lo 2-term,
// V single fp16). Triangle-balanced CTA pairs, cp.async double-buffered.
// smem per buffer: 3 arrays x [32][72] floats = 27 KB; x2 = 54 KB.
// ---------------------------------------------------------------------------
#define KVS 72
#define ARR (32 * KVS)
#define ATTN_SMEM (2 * 3 * ARR * 4)

__global__ __launch_bounds__(128, 3) void attn_kernel(float* __restrict__ out)
{
    extern __shared__ float sm[];

    const int b    = blockIdx.y;
    const int tid  = threadIdx.x;
    const int lane = tid & 31, warp = tid >> 5;
    const int lg = lane >> 2, lr = lane & 3;
    const int wrow = warp * 16;

    const unsigned* gkh = g_kh + (size_t)b * 32 * 2048;
    const unsigned* gkl = g_kl + (size_t)b * 32 * 2048;
    const unsigned* gvf = g_vf + (size_t)b * 1024 * DD;

    const float NEG_INF = -CUDART_INF_F;
    const float SCL = 0.125f * 1.44269504088896340736f;  // (1/sqrt(64)) * log2(e)

    auto stage = [&](int buf, int st) {
        float* kh = sm + (buf * 3 + 0) * ARR;
        float* kl = sm + (buf * 3 + 1) * ARR;
        float* vf = sm + (buf * 3 + 2) * ARR;
#pragma unroll
        for (int u = 0; u < 4; u++) {
            const int cid = tid + 128 * u;
            const int row = cid >> 4;
            const int off = (cid & 15) * 4;
            cpa16(kh + row * KVS + off, gkh + row * 2048 + st * 64 + off);
            cpa16(kl + row * KVS + off, gkl + row * 2048 + st * 64 + off);
            cpa16(vf + row * KVS + off, gvf + (st * 32 + row) * DD + off);
        }
        asm volatile("cp.async.commit_group;" ::: "memory");
    };

    for (int half = 0; half < 2; half++) {
        const int qt = half ? blockIdx.x : 31 - blockIdx.x;
        const int rowg = b * TT + qt * 64;
        const int grow1 = qt * 64 + wrow + lg;
        const int grow2 = grow1 + 8;

        // ---- Q fragments (prescaled by SCL, bf16 hi/lo split) ----
        unsigned qh[4][4], ql[4][4];
        {
            const float* q1 = g_q + (rowg + wrow + lg) * DD;
            const float* q2 = q1 + 8 * DD;
#pragma unroll
            for (int c = 0; c < 4; c++) {
                const int cc = 16 * c + 2 * lr;
                float2 a  = *(const float2*)(q1 + cc);
                float2 bq = *(const float2*)(q2 + cc);
                float2 a8 = *(const float2*)(q1 + cc + 8);
                float2 b8 = *(const float2*)(q2 + cc + 8);
                split2(a.x  * SCL, a.y  * SCL, qh[c][0], ql[c][0]);
                split2(bq.x * SCL, bq.y * SCL, qh[c][1], ql[c][1]);
                split2(a8.x * SCL, a8.y * SCL, qh[c][2], ql[c][2]);
                split2(b8.x * SCL, b8.y * SCL, qh[c][3], ql[c][3]);
            }
        }

        float4 oc[8];
#pragma unroll
        for (int j = 0; j < 8; j++) oc[j] = make_float4(0.f, 0.f, 0.f, 0.f);
        float m1 = -1e30f, m2 = -1e30f, l1 = 0.f, l2 = 0.f;

        __syncthreads();          // protect smem reuse across halves
        stage(0, 0);
        int buf = 0;

        for (int st = 0; st <= qt; st++) {
            asm volatile("cp.async.wait_group 0;" ::: "memory");
            __syncthreads();
            if (st < qt) stage(buf ^ 1, st + 1);

            const float* khb = sm + (buf * 3 + 0) * ARR;
            const float* klb = sm + (buf * 3 + 1) * ARR;
            const float* vfb = sm + (buf * 3 + 2) * ARR;

            // ---- S = Q K^T (3-term bf16), log2 domain ----
            float4 sc[8];
#pragma unroll
            for (int j = 0; j < 8; j++) sc[j] = make_float4(0.f, 0.f, 0.f, 0.f);
#pragma unroll
            for (int c = 0; c < 4; c++) {
                const int ra = (8 * c + lr) * KVS + lg;
                const int rb = (8 * c + lr + 4) * KVS + lg;
#pragma unroll
                for (int j = 0; j < 8; j++) {
                    const unsigned kh0 = __float_as_uint(khb[ra + j * 8]);
                    const unsigned kh1 = __float_as_uint(khb[rb + j * 8]);
                    const unsigned kl0 = __float_as_uint(klb[ra + j * 8]);
                    const unsigned kl1 = __float_as_uint(klb[rb + j * 8]);
                    mma16(sc[j], qh[c], kh0, kh1);
                    mma16(sc[j], ql[c], kh0, kh1);
                    mma16(sc[j], qh[c], kl0, kl1);
                }
            }

            // ---- mask (diag hoisted; zero-quirk always) ----
            if (st == qt) {
                const int cbv = st * 64 + 2 * lr;
#pragma unroll
                for (int j = 0; j < 8; j++) {
                    const int c0g = cbv + 8 * j;
                    if (c0g     > grow1 || sc[j].x == 0.0f) sc[j].x = NEG_INF;
                    if (c0g + 1 > grow1 || sc[j].y == 0.0f) sc[j].y = NEG_INF;
                    if (c0g     > grow2 || sc[j].z == 0.0f) sc[j].z = NEG_INF;
                    if (c0g + 1 > grow2 || sc[j].w == 0.0f) sc[j].w = NEG_INF;
                }
            } else {
#pragma unroll
                for (int j = 0; j < 8; j++) {
                    if (sc[j].x == 0.0f) sc[j].x = NEG_INF;
                    if (sc[j].y == 0.0f) sc[j].y = NEG_INF;
                    if (sc[j].z == 0.0f) sc[j].z = NEG_INF;
                    if (sc[j].w == 0.0f) sc[j].w = NEG_INF;
                }
            }

            // ---- online softmax (exp2) ----
            float rm1 = NEG_INF, rm2 = NEG_INF;
#pragma unroll
            for (int j = 0; j < 8; j++) {
                rm1 = fmaxf(rm1, fmaxf(sc[j].x, sc[j].y));
                rm2 = fmaxf(rm2, fmaxf(sc[j].z, sc[j].w));
            }
            rm1 = fmaxf(rm1, __shfl_xor_sync(0xffffffffu, rm1, 1));
            rm1 = fmaxf(rm1, __shfl_xor_sync(0xffffffffu, rm1, 2));
            rm2 = fmaxf(rm2, __shfl_xor_sync(0xffffffffu, rm2, 1));
            rm2 = fmaxf(rm2, __shfl_xor_sync(0xffffffffu, rm2, 2));

            const float mn1 = fmaxf(m1, rm1);
            const float mn2 = fmaxf(m2, rm2);
            const float fac1 = ex2(m1 - mn1);
            const float fac2 = ex2(m2 - mn2);

            unsigned pha[8], phb[8], pla[8], plb[8];   // fp16x2 packs
            float ps1 = 0.f, ps2 = 0.f;
#pragma unroll
            for (int j = 0; j < 8; j++) {
                const float px = ex2(sc[j].x - mn1);
                const float py = ex2(sc[j].y - mn1);
                const float pz = ex2(sc[j].z - mn2);
                const float pw = ex2(sc[j].w - mn2);
                ps1 += px + py;
                ps2 += pz + pw;
                splith2(px, py, pha[j], pla[j]);
                splith2(pz, pw, phb[j], plb[j]);
            }
            ps1 += __shfl_xor_sync(0xffffffffu, ps1, 1);
            ps1 += __shfl_xor_sync(0xffffffffu, ps1, 2);
            ps2 += __shfl_xor_sync(0xffffffffu, ps2, 1);
            ps2 += __shfl_xor_sync(0xffffffffu, ps2, 2);

            l1 = l1 * fac1 + ps1;  m1 = mn1;
            l2 = l2 * fac2 + ps2;  m2 = mn2;
#pragma unroll
            for (int j = 0; j < 8; j++) {
                oc[j].x *= fac1; oc[j].y *= fac1;
                oc[j].z *= fac2; oc[j].w *= fac2;
            }

            // ---- O += P V (fp16: 2-term P, single V) ----
#pragma unroll
            for (int c = 0; c < 4; c++) {
                const unsigned ah[4] = {pha[2 * c], phb[2 * c], pha[2 * c + 1], phb[2 * c + 1]};
                const unsigned al[4] = {pla[2 * c], plb[2 * c], pla[2 * c + 1], plb[2 * c + 1]};
                const int ra = (8 * c + lr) * KVS + lg;
                const int rb = (8 * c + lr + 4) * KVS + lg;
#pragma unroll
                for (int j = 0; j < 8; j++) {
                    const unsigned vf0 = __float_as_uint(vfb[ra + j * 8]);
                    const unsigned vf1 = __float_as_uint(vfb[rb + j * 8]);
                    mma16h(oc[j], ah, vf0, vf1);
                    mma16h(oc[j], al, vf0, vf1);
                }
            }
            buf ^= 1;
        }

        // ---- epilogue ----
        const float inv1 = 1.0f / l1;
        const float inv2 = 1.0f / l2;
        const int ob1 = (rowg + wrow + lg) * DD + 2 * lr;
        const int ob2 = ob1 + 8 * DD;
#pragma unroll
        for (int j = 0; j < 8; j++) {
            *(float2*)&out[ob1 + 8 * j] = make_float2(oc[j].x * inv1, oc[j].y * inv1);
            *(float2*)&out[ob2 + 8 * j] = make_float2(oc[j].z * inv2, oc[j].w * inv2);
        }
    }
}

// ---------------------------------------------------------------------------
extern "C" void kernel_launch(void* const* d_in, const int* in_sizes, int n_in,
                              void* d_out, int out_size)
{
    (void)in_sizes; (void)n_in; (void)out_size;
    const float* x  = (const float*)d_in[0];
    const float* Wq = (const float*)d_in[1];
    const float* Wk = (const float*)d_in[2];
    const float* Wv = (const float*)d_in[3];
    float* out = (float*)d_out;

    cudaFuncSetAttribute(proj_kernel,
                         cudaFuncAttributeMaxDynamicSharedMemorySize, PROJ_SMEM);
    cudaFuncSetAttribute(attn_kernel,
                         cudaFuncAttributeMaxDynamicSharedMemorySize, ATTN_SMEM);

    wsplit_kernel<<<192, 192>>>(Wq, Wk, Wv);
    proj_kernel<<<dim3(BB * TT / 128, 2), 128, PROJ_SMEM>>>(x);
    attn_kernel<<<dim3(16, BB), 128, ATTN_SMEM>>>(out);
}

// round 9
// speedup vs baseline: 4.1378x; 1.0158x over previous
#include <cuda_runtime.h>
#include <cuda_fp16.h>
#include <math_constants.h>

#define BB 16
#define TT 2048
#define CC 384
#define DD 64

// q fp32; k packed fp16x2 single-precision; v packed fp16x2 single-precision
__device__ float    g_q[BB * TT * DD];
__device__ unsigned g_kf[BB * 32 * TT];        // [b][dp][t]  pack(k[t][2dp], k[t][2dp+1])
__device__ unsigned g_vf[BB * (TT / 2) * DD];  // [b][tp][d]  pack(v[2tp][d], v[2tp+1][d])
// fused W pre-split (bf16 hi/lo): [kp 0..191][n 0..191]
__device__ unsigned g_wh[192 * 192];
__device__ unsigned g_wl[192 * 192];

// ---- helpers ------------------------------------------------------------
__device__ __forceinline__ void split2(float a, float b, unsigned& hi, unsigned& lo) {
    unsigned h;
    asm("cvt.rn.bf16x2.f32 %0, %1, %2;" : "=r"(h) : "f"(b), "f"(a));
    float ha = __uint_as_float(h << 16);
    float hb = __uint_as_float(h & 0xffff0000u);
    unsigned l;
    asm("cvt.rn.bf16x2.f32 %0, %1, %2;" : "=r"(l) : "f"(b - hb), "f"(a - ha));
    hi = h; lo = l;
}
__device__ __forceinline__ unsigned packh2(float a, float b) {
    unsigned r;
    asm("cvt.rn.f16x2.f32 %0, %1, %2;" : "=r"(r) : "f"(b), "f"(a));
    return r;
}
__device__ __forceinline__ void splith2(float a, float b, unsigned& hi, unsigned& lo) {
    unsigned h;
    asm("cvt.rn.f16x2.f32 %0, %1, %2;" : "=r"(h) : "f"(b), "f"(a));
    __half2 hh = *reinterpret_cast<__half2*>(&h);
    float2 hf = __half22float2(hh);
    unsigned l;
    asm("cvt.rn.f16x2.f32 %0, %1, %2;" : "=r"(l) : "f"(b - hf.y), "f"(a - hf.x));
    hi = h; lo = l;
}
__device__ __forceinline__ void mma16(float4& c, const unsigned a[4],
                                      unsigned b0, unsigned b1) {
    asm("mma.sync.aligned.m16n8k16.row.col.f32.bf16.bf16.f32 "
        "{%0,%1,%2,%3},{%4,%5,%6,%7},{%8,%9},{%0,%1,%2,%3};"
        : "+f"(c.x), "+f"(c.y), "+f"(c.z), "+f"(c.w)
        : "r"(a[0]), "r"(a[1]), "r"(a[2]), "r"(a[3]), "r"(b0), "r"(b1));
}
__device__ __forceinline__ void mma16h(float4& c, const unsigned a[4],
                                       unsigned b0, unsigned b1) {
    asm("mma.sync.aligned.m16n8k16.row.col.f32.f16.f16.f32 "
        "{%0,%1,%2,%3},{%4,%5,%6,%7},{%8,%9},{%0,%1,%2,%3};"
        : "+f"(c.x), "+f"(c.y), "+f"(c.z), "+f"(c.w)
        : "r"(a[0]), "r"(a[1]), "r"(a[2]), "r"(a[3]), "r"(b0), "r"(b1));
}
__device__ __forceinline__ void cpa16(const void* smem_dst, const void* gsrc) {
    unsigned d = (unsigned)__cvta_generic_to_shared(smem_dst);
    asm volatile("cp.async.cg.shared.global [%0], [%1], 16;" :: "r"(d), "l"(gsrc));
}
__device__ __forceinline__ float ex2(float x) {
    float r;
    asm("ex2.approx.f32 %0, %1;" : "=f"(r) : "f"(x));
    return r;
}

// ---------------------------------------------------------------------------
// Kernel 0: one-shot W split. 192 blocks x 192 threads.
// ---------------------------------------------------------------------------
__global__ void wsplit_kernel(const float* __restrict__ Wq,
                              const float* __restrict__ Wk,
                              const float* __restrict__ Wv)
{
    const int kp = blockIdx.x;
    const int n  = threadIdx.x;
    const float* W = (n < 64) ? Wq : (n < 128) ? Wk : Wv;
    const int c = n & 63;
    unsigned h, l;
    split2(W[(2 * kp) * DD + c], W[(2 * kp + 1) * DD + c], h, l);
    g_wh[kp * 192 + n] = h;
    g_wl[kp * 192 + n] = l;
}

// ---------------------------------------------------------------------------
// Kernel 1: fused QKV projection, bf16 3-term mma.
// grid (256 row-blocks of 128, 2 col-blocks of 96). 256 threads, 8 warps,
// warp-tile 16 rows x 96 cols. More warps/SM to hide staging latency.
// ---------------------------------------------------------------------------
#define XSR 68
#define WST 100
#define PROJ_SMEM ((128 * XSR + 2 * 32 * WST) * 4)

__global__ __launch_bounds__(256, 2) void proj_kernel(const float* __restrict__ x)
{
    extern __shared__ float psm[];
    float* xs  = psm;
    float* wph = xs + 128 * XSR;
    float* wpl = wph + 32 * WST;

    const int tid  = threadIdx.x;
    const int lane = tid & 31, warp = tid >> 5;
    const int lg = lane >> 2, lr = lane & 3;
    const int rowBase = blockIdx.x * 128;
    const int cb = blockIdx.y;

    float4 acc[12];
#pragma unroll
    for (int j = 0; j < 12; j++) acc[j] = make_float4(0.f, 0.f, 0.f, 0.f);

    for (int kk = 0; kk < CC; kk += 64) {
#pragma unroll
        for (int u = 0; u < 8; u++) {
            const int cid = tid + 256 * u;       // 0..2047
            const int row = cid >> 4;
            const int off = (cid & 15) * 4;
            cpa16(xs + row * XSR + off, x + (size_t)(rowBase + row) * CC + kk + off);
        }
#pragma unroll
        for (int u = 0; u < 3; u++) {
            const int cid = tid + 256 * u;       // 0..767
            const int row = cid / 24;
            const int off = (cid % 24) * 4;
            cpa16(wph + row * WST + off, g_wh + (kk / 2 + row) * 192 + cb * 96 + off);
            cpa16(wpl + row * WST + off, g_wl + (kk / 2 + row) * 192 + cb * 96 + off);
        }
        asm volatile("cp.async.commit_group;" ::: "memory");
        asm volatile("cp.async.wait_group 0;" ::: "memory");
        __syncthreads();

#pragma unroll
        for (int c = 0; c < 4; c++) {
            unsigned ah[4], al[4];
            {
                const int rb0 = warp * 16 + lg;
                const int k0  = 16 * c + 2 * lr;
                float2 p0 = *(float2*)&xs[rb0 * XSR + k0];
                float2 p1 = *(float2*)&xs[(rb0 + 8) * XSR + k0];
                float2 p2 = *(float2*)&xs[rb0 * XSR + k0 + 8];
                float2 p3 = *(float2*)&xs[(rb0 + 8) * XSR + k0 + 8];
                split2(p0.x, p0.y, ah[0], al[0]);
                split2(p1.x, p1.y, ah[1], al[1]);
                split2(p2.x, p2.y, ah[2], al[2]);
                split2(p3.x, p3.y, ah[3], al[3]);
            }
#pragma unroll
            for (int j = 0; j < 12; j++) {
                const unsigned bh0 = __float_as_uint(wph[(8 * c + lr) * WST + j * 8 + lg]);
                const unsigned bh1 = __float_as_uint(wph[(8 * c + lr + 4) * WST + j * 8 + lg]);
                const unsigned bl0 = __float_as_uint(wpl[(8 * c + lr) * WST + j * 8 + lg]);
                const unsigned bl1 = __float_as_uint(wpl[(8 * c + lr + 4) * WST + j * 8 + lg]);
                mma16(acc[j], ah, bh0, bh1);
                mma16(acc[j], al, bh0, bh1);
                mma16(acc[j], ah, bl0, bl1);
            }
        }
        __syncthreads();
    }

    // ---- epilogue: q(fp32) / k(packed fp16 [dp][t]) / v(packed fp16 [tp][d]) ----
    {
        const int r0 = rowBase + warp * 16 + lg;
        const int b  = r0 >> 11;
        const int t  = r0 & 2047;
#pragma unroll
        for (int j = 0; j < 12; j++) {
            const int gc = cb * 96 + j * 8 + 2 * lr;
            float4 a = acc[j];
            if (gc < 64) {
                *(float2*)&g_q[r0 * DD + gc]       = make_float2(a.x, a.y);
                *(float2*)&g_q[(r0 + 8) * DD + gc] = make_float2(a.z, a.w);
            } else if (gc < 128) {
                const int dp = (gc - 64) >> 1;
                g_kf[((size_t)b * 32 + dp) * 2048 + t]     = packh2(a.x, a.y);
                g_kf[((size_t)b * 32 + dp) * 2048 + t + 8] = packh2(a.z, a.w);
            } else {
                const int d = gc - 128;
                float ox = __shfl_xor_sync(0xffffffffu, a.x, 4);
                float oy = __shfl_xor_sync(0xffffffffu, a.y, 4);
                float oz = __shfl_xor_sync(0xffffffffu, a.z, 4);
                float ow = __shfl_xor_sync(0xffffffffu, a.w, 4);
                if ((lg & 1) == 0) {
                    const int sp0 = r0 >> 1;
                    *(uint2*)&g_vf[(size_t)sp0 * DD + d] =
                        make_uint2(packh2(a.x, ox), packh2(a.y, oy));
                    const int sp1 = (r0 + 8) >> 1;
                    *(uint2*)&g_vf[(size_t)sp1 * DD + d] =
                        make_uint2(packh2(a.z, oz), packh2(a.w, ow));
                }
            }
        }
    }
}

// ---------------------------------------------------------------------------
// Kernel 2: flash attention. QK: fp16 (Q hi/lo 2-term, K single). PV: fp16
// (P hi/lo 2-term, V single). Triangle-balanced CTA pairs, cp.async
// double-buffered. smem per buffer: 2 x [32][72] floats = 18 KB; x2 = 36 KB.
// ---------------------------------------------------------------------------
#define KVS 72
#define ARR (32 * KVS)
#define ATTN_SMEM (2 * 2 * ARR * 4)

__global__ __launch_bounds__(128, 3) void attn_kernel(float* __restrict__ out)
{
    extern __shared__ float sm[];

    const int b    = blockIdx.y;
    const int tid  = threadIdx.x;
    const int lane = tid & 31, warp = tid >> 5;
    const int lg = lane >> 2, lr = lane & 3;
    const int wrow = warp * 16;

    const unsigned* gkf = g_kf + (size_t)b * 32 * 2048;
    const unsigned* gvf = g_vf + (size_t)b * 1024 * DD;

    const float NEG_INF = -CUDART_INF_F;
    const float SCL = 0.125f * 1.44269504088896340736f;  // (1/sqrt(64)) * log2(e)

    auto stage = [&](int buf, int st) {
        float* kf = sm + (buf * 2 + 0) * ARR;
        float* vf = sm + (buf * 2 + 1) * ARR;
#pragma unroll
        for (int u = 0; u < 4; u++) {
            const int cid = tid + 128 * u;
            const int row = cid >> 4;
            const int off = (cid & 15) * 4;
            cpa16(kf + row * KVS + off, gkf + row * 2048 + st * 64 + off);
            cpa16(vf + row * KVS + off, gvf + (st * 32 + row) * DD + off);
        }
        asm volatile("cp.async.commit_group;" ::: "memory");
    };

    for (int half = 0; half < 2; half++) {
        const int qt = half ? blockIdx.x : 31 - blockIdx.x;
        const int rowg = b * TT + qt * 64;
        const int grow1 = qt * 64 + wrow + lg;
        const int grow2 = grow1 + 8;

        // ---- Q fragments (prescaled by SCL, fp16 hi/lo split) ----
        unsigned qh[4][4], ql[4][4];
        {
            const float* q1 = g_q + (rowg + wrow + lg) * DD;
            const float* q2 = q1 + 8 * DD;
#pragma unroll
            for (int c = 0; c < 4; c++) {
                const int cc = 16 * c + 2 * lr;
                float2 a  = *(const float2*)(q1 + cc);
                float2 bq = *(const float2*)(q2 + cc);
                float2 a8 = *(const float2*)(q1 + cc + 8);
                float2 b8 = *(const float2*)(q2 + cc + 8);
                splith2(a.x  * SCL, a.y  * SCL, qh[c][0], ql[c][0]);
                splith2(bq.x * SCL, bq.y * SCL, qh[c][1], ql[c][1]);
                splith2(a8.x * SCL, a8.y * SCL, qh[c][2], ql[c][2]);
                splith2(b8.x * SCL, b8.y * SCL, qh[c][3], ql[c][3]);
            }
        }

        float4 oc[8];
#pragma unroll
        for (int j = 0; j < 8; j++) oc[j] = make_float4(0.f, 0.f, 0.f, 0.f);
        float m1 = -1e30f, m2 = -1e30f, l1 = 0.f, l2 = 0.f;

        __syncthreads();          // protect smem reuse across halves
        stage(0, 0);
        int buf = 0;

        for (int st = 0; st <= qt; st++) {
            asm volatile("cp.async.wait_group 0;" ::: "memory");
            __syncthreads();
            if (st < qt) stage(buf ^ 1, st + 1);

            const float* kfb = sm + (buf * 2 + 0) * ARR;
            const float* vfb = sm + (buf * 2 + 1) * ARR;

            // ---- S = Q K^T (fp16: 2-term Q, single K), log2 domain ----
            float4 sc[8];
#pragma unroll
            for (int j = 0; j < 8; j++) sc[j] = make_float4(0.f, 0.f, 0.f, 0.f);
#pragma unroll
            for (int c = 0; c < 4; c++) {
                const int ra = (8 * c + lr) * KVS + lg;
                const int rb = (8 * c + lr + 4) * KVS + lg;
#pragma unroll
                for (int j = 0; j < 8; j++) {
                    const unsigned kf0 = __float_as_uint(kfb[ra + j * 8]);
                    const unsigned kf1 = __float_as_uint(kfb[rb + j * 8]);
                    mma16h(sc[j], qh[c], kf0, kf1);
                    mma16h(sc[j], ql[c], kf0, kf1);
                }
            }

            // ---- mask (diag hoisted; zero-quirk always) ----
            if (st == qt) {
                const int cbv = st * 64 + 2 * lr;
#pragma unroll
                for (int j = 0; j < 8; j++) {
                    const int c0g = cbv + 8 * j;
                    if (c0g     > grow1 || sc[j].x == 0.0f) sc[j].x = NEG_INF;
                    if (c0g + 1 > grow1 || sc[j].y == 0.0f) sc[j].y = NEG_INF;
                    if (c0g     > grow2 || sc[j].z == 0.0f) sc[j].z = NEG_INF;
                    if (c0g + 1 > grow2 || sc[j].w == 0.0f) sc[j].w = NEG_INF;
                }
            } else {
#pragma unroll
                for (int j = 0; j < 8; j++) {
                    if (sc[j].x == 0.0f) sc[j].x = NEG_INF;
                    if (sc[j].y == 0.0f) sc[j].y = NEG_INF;
                    if (sc[j].z == 0.0f) sc[j].z = NEG_INF;
                    if (sc[j].w == 0.0f) sc[j].w = NEG_INF;
                }
            }

            // ---- online softmax (exp2) ----
            float rm1 = NEG_INF, rm2 = NEG_INF;
#pragma unroll
            for (int j = 0; j < 8; j++) {
                rm1 = fmaxf(rm1, fmaxf(sc[j].x, sc[j].y));
                rm2 = fmaxf(rm2, fmaxf(sc[j].z, sc[j].w));
            }
            rm1 = fmaxf(rm1, __shfl_xor_sync(0xffffffffu, rm1, 1));
            rm1 = fmaxf(rm1, __shfl_xor_sync(0xffffffffu, rm1, 2));
            rm2 = fmaxf(rm2, __shfl_xor_sync(0xffffffffu, rm2, 1));
            rm2 = fmaxf(rm2, __shfl_xor_sync(0xffffffffu, rm2, 2));

            const float mn1 = fmaxf(m1, rm1);
            const float mn2 = fmaxf(m2, rm2);
            const float fac1 = ex2(m1 - mn1);
            const float fac2 = ex2(m2 - mn2);

            unsigned pha[8], phb[8], pla[8], plb[8];   // fp16x2 packs
            float ps1 = 0.f, ps2 = 0.f;
#pragma unroll
            for (int j = 0; j < 8; j++) {
                const float px = ex2(sc[j].x - mn1);
                const float py = ex2(sc[j].y - mn1);
                const float pz = ex2(sc[j].z - mn2);
                const float pw = ex2(sc[j].w - mn2);
                ps1 += px + py;
                ps2 += pz + pw;
                splith2(px, py, pha[j], pla[j]);
                splith2(pz, pw, phb[j], plb[j]);
            }
            ps1 += __shfl_xor_sync(0xffffffffu, ps1, 1);
            ps1 += __shfl_xor_sync(0xffffffffu, ps1, 2);
            ps2 += __shfl_xor_sync(0xffffffffu, ps2, 1);
            ps2 += __shfl_xor_sync(0xffffffffu, ps2, 2);

            l1 = l1 * fac1 + ps1;  m1 = mn1;
            l2 = l2 * fac2 + ps2;  m2 = mn2;
#pragma unroll
            for (int j = 0; j < 8; j++) {
                oc[j].x *= fac1; oc[j].y *= fac1;
                oc[j].z *= fac2; oc[j].w *= fac2;
            }

            // ---- O += P V (fp16: 2-term P, single V) ----
#pragma unroll
            for (int c = 0; c < 4; c++) {
                const unsigned ah[4] = {pha[2 * c], phb[2 * c], pha[2 * c + 1], phb[2 * c + 1]};
                const unsigned al[4] = {pla[2 * c], plb[2 * c], pla[2 * c + 1], plb[2 * c + 1]};
                const int ra = (8 * c + lr) * KVS + lg;
                const int rb = (8 * c + lr + 4) * KVS + lg;
#pragma unroll
                for (int j = 0; j < 8; j++) {
                    const unsigned vf0 = __float_as_uint(vfb[ra + j * 8]);
                    const unsigned vf1 = __float_as_uint(vfb[rb + j * 8]);
                    mma16h(oc[j], ah, vf0, vf1);
                    mma16h(oc[j], al, vf0, vf1);
                }
            }
            buf ^= 1;
        }

        // ---- epilogue ----
        const float inv1 = 1.0f / l1;
        const float inv2 = 1.0f / l2;
        const int ob1 = (rowg + wrow + lg) * DD + 2 * lr;
        const int ob2 = ob1 + 8 * DD;
#pragma unroll
        for (int j = 0; j < 8; j++) {
            *(float2*)&out[ob1 + 8 * j] = make_float2(oc[j].x * inv1, oc[j].y * inv1);
            *(float2*)&out[ob2 + 8 * j] = make_float2(oc[j].z * inv2, oc[j].w * inv2);
        }
    }
}

// ---------------------------------------------------------------------------
extern "C" void kernel_launch(void* const* d_in, const int* in_sizes, int n_in,
                              void* d_out, int out_size)
{
    (void)in_sizes; (void)n_in; (void)out_size;
    const float* x  = (const float*)d_in[0];
    const float* Wq = (const float*)d_in[1];
    const float* Wk = (const float*)d_in[2];
    const float* Wv = (const float*)d_in[3];
    float* out = (float*)d_out;

    cudaFuncSetAttribute(proj_kernel,
                         cudaFuncAttributeMaxDynamicSharedMemorySize, PROJ_SMEM);
    cudaFuncSetAttribute(attn_kernel,
                         cudaFuncAttributeMaxDynamicSharedMemorySize, ATTN_SMEM);

    wsplit_kernel<<<192, 192>>>(Wq, Wk, Wv);
    proj_kernel<<<dim3(BB * TT / 128, 2), 256, PROJ_SMEM>>>(x);
    attn_kernel<<<dim3(16, BB), 128, ATTN_SMEM>>>(out);
}